// round 14
// baseline (speedup 1.0000x reference)
#include <cuda_runtime.h>
#include <cuda_bf16.h>
#include <cuda_fp16.h>
#include <math.h>
#include <stdint.h>

#define BB   2
#define SS   2048
#define DD   1024
#define HH   16
#define DHH  64
#define NBB  32
#define MLPD 4096
#define TOK  (BB*SS)
#define HN   (HH*NBB)
#define QKVD 3072
#define BH   (BB*HH)
#define NT   (TOK/128)

__device__ __align__(128) __nv_bfloat16 g_xh [TOK*DD];
__device__ __align__(128) __nv_bfloat16 g_ah [TOK*DD];
__device__ __align__(128) float         g_x  [TOK*DD];
__device__ __align__(128) __nv_bfloat16 g_y  [TOK*DD];        // fp16 payload
__device__ __align__(128) __nv_bfloat16 g_h1 [TOK*MLPD];      // fp16 payload
__device__ __align__(128) float         g_bpart[2*HH*NT*NBB];
__device__ __align__(128) __nv_bfloat16 g_wqkvh[QKVD*DD];
__device__ __align__(128) __nv_bfloat16 g_woh [DD*DD];
__device__ __align__(128) __nv_bfloat16 g_w1 [MLPD*DD];       // fp16 payload
__device__ __align__(128) __nv_bfloat16 g_w2 [DD*MLPD];       // fp16 payload
__device__ __align__(128) __nv_bfloat16 g_Qa [BH*SS*96];
__device__ __align__(128) __nv_bfloat16 g_Ka [BH*SS*96];
__device__ __align__(128) __nv_bfloat16 g_Vb [BH*SS*64];
__device__ __align__(128) __nv_bfloat16 g_wt [2*HH*NBB*64];

__device__ __forceinline__ uint32_t smem_u32(const void* p){
    uint32_t a;
    asm("{ .reg .u64 t; cvta.to.shared.u64 t, %1; cvt.u32.u64 %0, t; }" : "=r"(a) : "l"(p));
    return a;
}
#define CPA16(dst, src) \
    asm volatile("cp.async.cg.shared.global [%0], [%1], 16;" :: "r"(dst), "l"(src))
#define CP_COMMIT() asm volatile("cp.async.commit_group;" ::: "memory")
#define CP_WAIT2()  asm volatile("cp.async.wait_group 2;" ::: "memory")
#define CP_WAIT1()  asm volatile("cp.async.wait_group 1;" ::: "memory")
#define CP_WAIT0()  asm volatile("cp.async.wait_group 0;" ::: "memory")
#define LDSM4(r, addr) \
    asm volatile("ldmatrix.sync.aligned.m8n8.x4.shared.b16 {%0,%1,%2,%3}, [%4];" \
        : "=r"((r)[0]), "=r"((r)[1]), "=r"((r)[2]), "=r"((r)[3]) : "r"(addr))
#define LDSM4T(r, addr) \
    asm volatile("ldmatrix.sync.aligned.m8n8.x4.trans.shared.b16 {%0,%1,%2,%3}, [%4];" \
        : "=r"((r)[0]), "=r"((r)[1]), "=r"((r)[2]), "=r"((r)[3]) : "r"(addr))
#define MMA16816(d, a, b0, b1) \
    asm volatile("mma.sync.aligned.m16n8k16.row.col.f32.bf16.bf16.f32 " \
        "{%0,%1,%2,%3}, {%4,%5,%6,%7}, {%8,%9}, {%0,%1,%2,%3};" \
        : "+f"((d)[0]), "+f"((d)[1]), "+f"((d)[2]), "+f"((d)[3]) \
        : "r"((a)[0]), "r"((a)[1]), "r"((a)[2]), "r"((a)[3]), "r"(b0), "r"(b1))
#define MMAH16816(d, a, b0, b1) \
    asm volatile("mma.sync.aligned.m16n8k16.row.col.f32.f16.f16.f32 " \
        "{%0,%1,%2,%3}, {%4,%5,%6,%7}, {%8,%9}, {%0,%1,%2,%3};" \
        : "+f"((d)[0]), "+f"((d)[1]), "+f"((d)[2]), "+f"((d)[3]) \
        : "r"((a)[0]), "r"((a)[1]), "r"((a)[2]), "r"((a)[3]), "r"(b0), "r"(b1))
#define PACKBF(d, lo, hi) \
    asm("cvt.rn.bf16x2.f32 %0, %1, %2;" : "=r"(d) : "f"(hi), "f"(lo))

// ===== mma.sync GEMM: CTA 256x128, warp 64x64, K-chunk 32, 4-stage, occ 1 =====
// EPI: 1 +res fp32 | 2 +bias,relu->fp16 | 3 +bias+res fp32 | 4 qkv->Qa/Ka/Vb
#define SB   24576u
#define GSM  (256*132*4)   // 135168 >= 4*SB

template<int EPI, int F16>
__global__ __launch_bounds__(256, 1) void mma_gemm(
    const __nv_bfloat16* __restrict__ A, const __nv_bfloat16* __restrict__ B,
    float* __restrict__ C, const float* __restrict__ bias, const float* __restrict__ res,
    __nv_bfloat16* __restrict__ Oh, __nv_bfloat16* __restrict__ Ol,
    __nv_bfloat16* __restrict__ Vo,
    int M, int N, int K)
{
    extern __shared__ char sm[];
    const uint32_t smu = smem_u32(sm);
    const int tid = threadIdx.x;
    const int wid = tid >> 5, lane = tid & 31;
    const int bm = blockIdx.y * 256, bn = blockIdx.x * 128;
    const int wm = wid >> 1, wn = wid & 1;      // warp tile 64x64

    // producer A: 1 thread per row (256 rows), 4x16B each
    const uint32_t swA = (uint32_t)((tid >> 1) & 3);
    uint32_t pdA[4];
    #pragma unroll
    for (int c = 0; c < 4; c++) pdA[c] = (uint32_t)(tid*64) + (((uint32_t)c ^ swA) << 4);
    const __nv_bfloat16* gA = A + (size_t)(bm + tid)*K;
    // producer B: 2 threads per row (128 rows), 2x16B each
    const int prB = tid >> 1, phB = tid & 1;
    const uint32_t swB = (uint32_t)((prB >> 1) & 3);
    const uint32_t pdB0 = (uint32_t)(prB*64) + ((((uint32_t)phB*2u + 0u) ^ swB) << 4);
    const uint32_t pdB1 = (uint32_t)(prB*64) + ((((uint32_t)phB*2u + 1u) ^ swB) << 4);
    const __nv_bfloat16* gB = B + (size_t)(bn + prB)*K + phB*16;

    const int g   = lane >> 3, rin = lane & 7;
    const int roff = (g & 1)*8 + rin;
    const uint32_t chi = (uint32_t)(g >> 1);
    uint32_t aRow[4], aSw[4], bRow[4], bSw[4];
    #pragma unroll
    for (int mi = 0; mi < 4; mi++){
        const int r = wm*64 + mi*16 + roff;
        aRow[mi] = (uint32_t)(r*64); aSw[mi] = (uint32_t)((r >> 1) & 3);
    }
    #pragma unroll
    for (int nj = 0; nj < 4; nj++){
        const int r = wn*64 + nj*16 + roff;
        bRow[nj] = 16384u + (uint32_t)(r*64); bSw[nj] = (uint32_t)((r >> 1) & 3);
    }

    float acc[4][8][4];
    #pragma unroll
    for (int mi = 0; mi < 4; mi++)
        #pragma unroll
        for (int nj = 0; nj < 8; nj++)
            #pragma unroll
            for (int e = 0; e < 4; e++) acc[mi][nj][e] = 0.f;

    auto issue = [&](int c, uint32_t st){
        const int kc = c << 5;
        #pragma unroll
        for (int cc = 0; cc < 4; cc++) CPA16(st + pdA[cc], gA + kc + cc*8);
        CPA16(st + 16384u + pdB0, gB + kc);
        CPA16(st + 16384u + pdB1, gB + kc + 8);
        CP_COMMIT();
    };

    const int nch = K >> 5;
    issue(0, smu);
    issue(1, smu + SB);
    issue(2, smu + 2u*SB);

    for (int c = 0; c < nch; c++){
        const uint32_t st = smu + (uint32_t)(c & 3)*SB;
        CP_WAIT2();
        __syncthreads();
        if (c + 3 < nch) issue(c + 3, smu + (uint32_t)((c + 3) & 3)*SB);
        else CP_COMMIT();

        #pragma unroll
        for (int ks = 0; ks < 2; ks++){
            const uint32_t ch = (uint32_t)(ks*2) + chi;
            uint32_t fa[4][4], fb[4][4];
            #pragma unroll
            for (int mi = 0; mi < 4; mi++)
                LDSM4(fa[mi], st + aRow[mi] + ((ch ^ aSw[mi]) << 4));
            #pragma unroll
            for (int nj = 0; nj < 4; nj++)
                LDSM4(fb[nj], st + bRow[nj] + ((ch ^ bSw[nj]) << 4));
            #pragma unroll
            for (int mi = 0; mi < 4; mi++)
                #pragma unroll
                for (int nj = 0; nj < 4; nj++)
                    #pragma unroll
                    for (int jl = 0; jl < 2; jl++){
                        if (F16) MMAH16816(acc[mi][nj*2 + jl], fa[mi], fb[nj][jl], fb[nj][2 + jl]);
                        else     MMA16816 (acc[mi][nj*2 + jl], fa[mi], fb[nj][jl], fb[nj][2 + jl]);
                    }
        }
    }
    CP_WAIT0();
    __syncthreads();

    float* Csm = (float*)sm;
    #pragma unroll
    for (int mi = 0; mi < 4; mi++)
        #pragma unroll
        for (int nj = 0; nj < 8; nj++){
            const int r  = wm*64 + mi*16 + (lane >> 2);
            const int cc = wn*64 + nj*8  + (lane & 3)*2;
            *(float2*)&Csm[r*132 + cc]       = make_float2(acc[mi][nj][0], acc[mi][nj][1]);
            *(float2*)&Csm[(r + 8)*132 + cc] = make_float2(acc[mi][nj][2], acc[mi][nj][3]);
        }
    __syncthreads();

    #pragma unroll 1
    for (int it = 0; it < 32; it++){
        const int i = it*256 + tid;
        const int row = i >> 5;
        const int cq  = (i & 31) << 2;
        const float* cp = Csm + row*132 + cq;
        float a0 = cp[0], a1 = cp[1], a2 = cp[2], a3 = cp[3];
        const size_t gb = (size_t)(bm + row)*N + bn + cq;
        if (EPI == 1){
            const float4 r4 = *(const float4*)(res + gb);
            float4 o = {a0 + r4.x, a1 + r4.y, a2 + r4.z, a3 + r4.w};
            *(float4*)(C + gb) = o;
        } else if (EPI == 2){
            const float4 b4 = *(const float4*)(bias + bn + cq);
            float v0 = fmaxf(a0 + b4.x, 0.f), v1 = fmaxf(a1 + b4.y, 0.f);
            float v2 = fmaxf(a2 + b4.z, 0.f), v3 = fmaxf(a3 + b4.w, 0.f);
            *(__half2*)((__half*)Oh + gb)     = __floats2half2_rn(v0, v1);
            *(__half2*)((__half*)Oh + gb + 2) = __floats2half2_rn(v2, v3);
        } else if (EPI == 3){
            const float4 b4 = *(const float4*)(bias + bn + cq);
            const float4 r4 = *(const float4*)(res + gb);
            float4 o = {a0 + b4.x + r4.x, a1 + b4.y + r4.y,
                        a2 + b4.z + r4.z, a3 + b4.w + r4.w};
            *(float4*)(C + gb) = o;
        } else {
            const int col = bn + cq;
            const int sel = col >> 10;
            const int h   = (col & 1023) >> 6;
            const int d   = col & 63;
            const int tv  = bm + row;
            const size_t bhs = ((size_t)(((tv >> 11)*HH) + h)*SS + (tv & 2047));
            const float QSC = 0.125f * 1.44269504088896340736f;
            if (sel == 0){
                __nv_bfloat162 o0; o0.x = __float2bfloat16(a0*QSC); o0.y = __float2bfloat16(a1*QSC);
                __nv_bfloat162 o1; o1.x = __float2bfloat16(a2*QSC); o1.y = __float2bfloat16(a3*QSC);
                *(__nv_bfloat162*)(Oh + bhs*96 + d)     = o0;
                *(__nv_bfloat162*)(Oh + bhs*96 + d + 2) = o1;
            } else if (sel == 1){
                __nv_bfloat162 o0; o0.x = __float2bfloat16(a0); o0.y = __float2bfloat16(a1);
                __nv_bfloat162 o1; o1.x = __float2bfloat16(a2); o1.y = __float2bfloat16(a3);
                *(__nv_bfloat162*)(Ol + bhs*96 + d)     = o0;
                *(__nv_bfloat162*)(Ol + bhs*96 + d + 2) = o1;
            } else {
                __nv_bfloat162 o0; o0.x = __float2bfloat16(a0); o0.y = __float2bfloat16(a1);
                __nv_bfloat162 o1; o1.x = __float2bfloat16(a2); o1.y = __float2bfloat16(a3);
                *(__nv_bfloat162*)(Vo + bhs*64 + d)     = o0;
                *(__nv_bfloat162*)(Vo + bhs*64 + d + 2) = o1;
            }
        }
    }
}

// ============ unified weight prep ============
__global__ __launch_bounds__(256) void wprep(
    const float* __restrict__ Wq, const float* __restrict__ Wk,
    const float* __restrict__ Wv, const float* __restrict__ Wo,
    const float* __restrict__ W1, const float* __restrict__ W2)
{
    __shared__ float t[32][33];
    const int id = blockIdx.x;
    const float* W; __nv_bfloat16* T; int K, N, bx, by, f16;
    if (id < 4096){
        const int s = id >> 10, r = id & 1023;
        if (s < 3){ W = s == 0 ? Wq : (s == 1 ? Wk : Wv); T = g_wqkvh + (size_t)s*DD*DD; }
        else      { W = Wo; T = g_woh; }
        K = DD; N = DD; bx = r & 31; by = r >> 5; f16 = 0;
    } else if (id < 8192){
        const int r = id - 4096; W = W1; T = g_w1; K = DD; N = MLPD;
        bx = r & 127; by = r >> 7; f16 = 1;
    } else {
        const int r = id - 8192; W = W2; T = g_w2; K = MLPD; N = DD;
        bx = r & 31; by = r >> 5; f16 = 1;
    }
    const int tx = threadIdx.x & 31, ty = threadIdx.x >> 5;
    const int k0 = by*32, n0 = bx*32;
    #pragma unroll
    for (int i = 0; i < 4; i++)
        t[ty + i*8][tx] = W[(size_t)(k0 + ty + i*8)*N + n0 + tx];
    __syncthreads();
    #pragma unroll
    for (int i = 0; i < 4; i++){
        const int n = n0 + ty + i*8;
        const float x = t[tx][ty + i*8];
        if (f16) ((__half*)T)[(size_t)n*K + k0 + tx] = __float2half(x);
        else     T[(size_t)n*K + k0 + tx] = __float2bfloat16(x);
    }
}

__global__ __launch_bounds__(256) void wtrans(
    const float* __restrict__ Whq, const float* __restrict__ Whk,
    __nv_bfloat16* __restrict__ WT)
{
    const int h = blockIdx.x, m = blockIdx.y;
    const float* src = m ? Whk : Whq;
    const float sc = m ? 1.f : (1.f/(0.125f*1.44269504088896340736f));
    for (int i = threadIdx.x; i < DHH*NBB; i += 256){
        const int f = i >> 5, n = i & 31;
        WT[(((size_t)m*HH + h)*NBB + n)*64 + f] =
            __float2bfloat16(src[((size_t)h*DHH + f)*NBB + n]*sc);
    }
}

// ============ LayerNorm: MODE 0 = bf16 out, 1 = fp16 out ============
template<int MODE>
__global__ __launch_bounds__(256) void ln_split(
    const float* __restrict__ in, const float* __restrict__ g,
    const float* __restrict__ bta, __nv_bfloat16* __restrict__ oh)
{
    __shared__ float red[256];
    const int t = blockIdx.x, tid = threadIdx.x;
    const float4 x = ((const float4*)(in + (size_t)t*DD))[tid];

    float sum = x.x + x.y + x.z + x.w;
    red[tid] = sum; __syncthreads();
    #pragma unroll
    for (int o = 128; o > 0; o >>= 1) { if (tid < o) red[tid] += red[tid+o]; __syncthreads(); }
    const float mu = red[0] * (1.0f/DD);
    __syncthreads();

    float d0 = x.x-mu, d1 = x.y-mu, d2 = x.z-mu, d3 = x.w-mu;
    red[tid] = d0*d0 + d1*d1 + d2*d2 + d3*d3; __syncthreads();
    #pragma unroll
    for (int o = 128; o > 0; o >>= 1) { if (tid < o) red[tid] += red[tid+o]; __syncthreads(); }
    const float rs = rsqrtf(red[0]*(1.0f/DD) + 1e-6f);

    const float4 gg = ((const float4*)g)[tid];
    const float4 bb = ((const float4*)bta)[tid];
    float y0 = d0*rs*gg.x + bb.x, y1 = d1*rs*gg.y + bb.y;
    float y2 = d2*rs*gg.z + bb.z, y3 = d3*rs*gg.w + bb.w;

    if (MODE == 0){
        __nv_bfloat162 hp0; hp0.x = __float2bfloat16(y0); hp0.y = __float2bfloat16(y1);
        __nv_bfloat162 hp1; hp1.x = __float2bfloat16(y2); hp1.y = __float2bfloat16(y3);
        __nv_bfloat162* ph = (__nv_bfloat162*)(oh + (size_t)t*DD);
        ph[tid*2] = hp0; ph[tid*2 + 1] = hp1;
    } else {
        __half2* ph = (__half2*)((__half*)oh + (size_t)t*DD);
        ph[tid*2]     = __floats2half2_rn(y0, y1);
        ph[tid*2 + 1] = __floats2half2_rn(y2, y3);
    }
}

// ============ bucket softmax via mma (static shift) + fused partial sums ============
#define B2SM 41472
__global__ __launch_bounds__(128) void bucket2(
    const __nv_bfloat16* __restrict__ Qa, const __nv_bfloat16* __restrict__ Ka,
    const __nv_bfloat16* __restrict__ WT, float* __restrict__ bpart,
    __nv_bfloat16* __restrict__ Qao, __nv_bfloat16* __restrict__ Kao)
{
    extern __shared__ char sm[];
    const uint32_t smu = smem_u32(sm);
    const int tid = threadIdx.x, wid = tid >> 5, lane = tid & 31;
    const int h = blockIdx.x;
    const int ty = blockIdx.y, bq = ty >> 4, sbase = (ty & 15)*128;
    const int bh = bq*HH + h;
    const uint32_t Qs = smu, Ks = smu + 16384u, Ws = smu + 32768u;
    float* csum = (float*)(sm + 40960);

    const size_t qa0 = ((size_t)bh*SS + sbase)*96;
    for (int i = tid; i < 128*8; i += 128){
        const int r = i >> 3, c = i & 7;
        const uint32_t off = (uint32_t)(r*128) + (uint32_t)((c ^ (r & 7)) << 4);
        CPA16(Qs + off, (const char*)(Qa + qa0 + (size_t)r*96 + c*8));
        CPA16(Ks + off, (const char*)(Ka + qa0 + (size_t)r*96 + c*8));
    }
    for (int i = tid; i < 2*32*8; i += 128){
        const int m = i >> 8, r = (i >> 3) & 31, c = i & 7;
        CPA16(Ws + (uint32_t)(m*4096) + (uint32_t)(r*128) + (uint32_t)((c ^ (r & 7)) << 4),
              (const char*)(WT + ((size_t)m*HH + h)*NBB*64 + (size_t)r*64 + c*8));
    }
    CP_COMMIT(); CP_WAIT0(); __syncthreads();

    const int grp = lane >> 3, rin = lane & 7;
    const int roff = (grp & 1)*8 + rin, chi = grp >> 1;
    const float BSC = 0.1f * 1.44269504088896340736f;

    #pragma unroll
    for (int m = 0; m < 2; m++){
        const uint32_t As = m ? Ks : Qs;
        const uint32_t Bs = Ws + (uint32_t)m*4096u;
        float acc[2][4][4];
        #pragma unroll
        for (int mi = 0; mi < 2; mi++)
            #pragma unroll
            for (int nj = 0; nj < 4; nj++)
                #pragma unroll
                for (int e = 0; e < 4; e++) acc[mi][nj][e] = 0.f;

        #pragma unroll
        for (int ks = 0; ks < 4; ks++){
            uint32_t fa[2][4], fb0[4], fb1[4];
            #pragma unroll
            for (int mi = 0; mi < 2; mi++){
                const int r = wid*32 + mi*16 + roff;
                LDSM4(fa[mi], As + (uint32_t)(r*128) + (uint32_t)(((2*ks + chi) ^ (r & 7)) << 4));
            }
            { const int r = roff;      LDSM4(fb0, Bs + (uint32_t)(r*128) + (uint32_t)(((2*ks + chi) ^ (r & 7)) << 4)); }
            { const int r = 16 + roff; LDSM4(fb1, Bs + (uint32_t)(r*128) + (uint32_t)(((2*ks + chi) ^ (r & 7)) << 4)); }
            #pragma unroll
            for (int mi = 0; mi < 2; mi++){
                MMA16816(acc[mi][0], fa[mi], fb0[0], fb0[2]);
                MMA16816(acc[mi][1], fa[mi], fb0[1], fb0[3]);
                MMA16816(acc[mi][2], fa[mi], fb1[0], fb1[2]);
                MMA16816(acc[mi][3], fa[mi], fb1[1], fb1[3]);
            }
        }

        float local8[8];
        #pragma unroll
        for (int e = 0; e < 8; e++) local8[e] = 0.f;

        #pragma unroll
        for (int mi = 0; mi < 2; mi++){
            float s0v = 0.f, s1v = 0.f;
            #pragma unroll
            for (int nj = 0; nj < 4; nj++){
                acc[mi][nj][0] = __expf(acc[mi][nj][0]); s0v += acc[mi][nj][0];
                acc[mi][nj][1] = __expf(acc[mi][nj][1]); s0v += acc[mi][nj][1];
                acc[mi][nj][2] = __expf(acc[mi][nj][2]); s1v += acc[mi][nj][2];
                acc[mi][nj][3] = __expf(acc[mi][nj][3]); s1v += acc[mi][nj][3];
            }
            s0v += __shfl_xor_sync(~0u, s0v, 1); s0v += __shfl_xor_sync(~0u, s0v, 2);
            s1v += __shfl_xor_sync(~0u, s1v, 1); s1v += __shfl_xor_sync(~0u, s1v, 2);
            const float i0 = 1.f/s0v, i1 = 1.f/s1v;
            const int r_lo = wid*32 + mi*16 + (lane >> 2);
            const int srow0 = sbase + r_lo, srow1 = srow0 + 8;
            __nv_bfloat16* oo = m ? Kao : Qao;
            const float sc = m ? 1.f : BSC;
            #pragma unroll
            for (int nj = 0; nj < 4; nj++){
                const int cc = nj*8 + (lane & 3)*2;
                float p0 = acc[mi][nj][0]*i0, p1 = acc[mi][nj][1]*i0;
                float p2 = acc[mi][nj][2]*i1, p3 = acc[mi][nj][3]*i1;
                local8[nj*2]     += p0 + p2;
                local8[nj*2 + 1] += p1 + p3;
                __nv_bfloat162 o0; o0.x = __float2bfloat16(p0*sc); o0.y = __float2bfloat16(p1*sc);
                __nv_bfloat162 o1; o1.x = __float2bfloat16(p2*sc); o1.y = __float2bfloat16(p3*sc);
                *(__nv_bfloat162*)(oo + ((size_t)bh*SS + srow0)*96 + 64 + cc) = o0;
                *(__nv_bfloat162*)(oo + ((size_t)bh*SS + srow1)*96 + 64 + cc) = o1;
            }
        }

        #pragma unroll
        for (int e = 0; e < 8; e++){
            local8[e] += __shfl_down_sync(~0u, local8[e], 16);
            local8[e] += __shfl_down_sync(~0u, local8[e], 8);
            local8[e] += __shfl_down_sync(~0u, local8[e], 4);
        }
        if ((lane >> 2) == 0){
            #pragma unroll
            for (int nj = 0; nj < 4; nj++){
                csum[wid*32 + nj*8 + lane*2]     = local8[nj*2];
                csum[wid*32 + nj*8 + lane*2 + 1] = local8[nj*2 + 1];
            }
        }
        __syncthreads();
        if (tid < 32){
            const float v = csum[tid] + csum[32 + tid] + csum[64 + tid] + csum[96 + tid];
            bpart[(((size_t)m*HH + h)*NT + ty)*NBB + tid] = v;
        }
        __syncthreads();
    }
}

// ============ flash attention: static-shift softmax ============
#define FSM 65536
#define CSH 24.0f
__global__ __launch_bounds__(256, 2) void flash_mma(
    const __nv_bfloat16* __restrict__ Qa, const __nv_bfloat16* __restrict__ Ka,
    const __nv_bfloat16* __restrict__ Vb, __nv_bfloat16* __restrict__ ah)
{
    extern __shared__ char sm[];
    const uint32_t smu = smem_u32(sm);
    const int tid = threadIdx.x, wid = tid >> 5, lane = tid & 31;
    const int bh = blockIdx.x, b = bh >> 4, h = bh & 15;
    const int q0 = blockIdx.y * 128;

    const uint32_t QC = smu, QB = smu + 16384u;
    const uint32_t ST0 = smu + 24576u;

    {
        const size_t qb0 = ((size_t)bh*SS + q0)*96;
        #pragma unroll
        for (int i = 0; i < 4; i++){
            const int q = tid + i*256, r = q >> 3, c = q & 7;
            CPA16(QC + (uint32_t)(r*128) + (uint32_t)(((c ^ (r & 7)) << 4)),
                  (const char*)(Qa + qb0 + (size_t)r*96 + c*8));
        }
        #pragma unroll
        for (int i = 0; i < 2; i++){
            const int q = tid + i*256, r = q >> 2, c = q & 3;
            CPA16(QB + (uint32_t)(r*64) + (uint32_t)(((c ^ ((r >> 1) & 3)) << 4)),
                  (const char*)(Qa + qb0 + (size_t)r*96 + 64 + c*8));
        }
        CP_COMMIT();
    }
    auto issueKV = [&](int it, uint32_t st){
        const size_t kb0 = ((size_t)bh*SS + it*64)*96;
        const size_t vb0 = ((size_t)bh*SS + it*64)*64;
        #pragma unroll
        for (int i = 0; i < 2; i++){
            const int q = tid + i*256, r = q >> 3, c = q & 7;
            CPA16(st + (uint32_t)(r*128) + (uint32_t)((c ^ (r & 7)) << 4),
                  (const char*)(Ka + kb0 + (size_t)r*96 + c*8));
        }
        {
            const int r = tid >> 2, c = tid & 3;
            CPA16(st + 8192u + (uint32_t)(r*64) + (uint32_t)((c ^ ((r >> 1) & 3)) << 4),
                  (const char*)(Ka + kb0 + (size_t)r*96 + 64 + c*8));
        }
        #pragma unroll
        for (int i = 0; i < 2; i++){
            const int q = tid + i*256, r = q >> 3, c = q & 7;
            CPA16(st + 12288u + (uint32_t)(r*128) + (uint32_t)((c ^ (r & 7)) << 4),
                  (const char*)(Vb + vb0 + (size_t)r*64 + c*8));
        }
        CP_COMMIT();
    };
    issueKV(0, ST0);
    issueKV(1, ST0 + 20480u);

    CP_WAIT2();
    __syncthreads();

    const int grp = lane >> 3, rin = lane & 7;
    const int roff = (grp & 1)*8 + rin, chi = grp >> 1;

    uint32_t qf[6][4];
    {
        const int r = wid*16 + roff;
        #pragma unroll
        for (int ks = 0; ks < 4; ks++)
            LDSM4(qf[ks], QC + (uint32_t)(r*128) + (uint32_t)(((2*ks + chi) ^ (r & 7)) << 4));
        #pragma unroll
        for (int ks = 0; ks < 2; ks++)
            LDSM4(qf[4 + ks], QB + (uint32_t)(r*64) + (uint32_t)(((2*ks + chi) ^ ((r >> 1) & 3)) << 4));
    }

    float oacc[8][4];
    #pragma unroll
    for (int nt = 0; nt < 8; nt++)
        #pragma unroll
        for (int e = 0; e < 4; e++) oacc[nt][e] = 0.f;
    float l0 = 0.f, l1 = 0.f;

    for (int it = 0; it < SS/64; it++){
        const uint32_t st = ST0 + (uint32_t)(it & 1)*20480u;
        if (it + 1 < SS/64) CP_WAIT1(); else CP_WAIT0();
        __syncthreads();

        float sacc[8][4];
        #pragma unroll
        for (int nt = 0; nt < 8; nt++)
            #pragma unroll
            for (int e = 0; e < 4; e++) sacc[nt][e] = 0.f;

        #pragma unroll
        for (int ks = 0; ks < 6; ks++){
            #pragma unroll
            for (int p = 0; p < 4; p++){
                uint32_t bf[4];
                const int r = p*16 + roff;
                if (ks < 4)
                    LDSM4(bf, st + (uint32_t)(r*128) + (uint32_t)(((2*ks + chi) ^ (r & 7)) << 4));
                else
                    LDSM4(bf, st + 8192u + (uint32_t)(r*64) + (uint32_t)(((2*(ks-4) + chi) ^ ((r >> 1) & 3)) << 4));
                MMA16816(sacc[2*p],     qf[ks], bf[0], bf[2]);
                MMA16816(sacc[2*p + 1], qf[ks], bf[1], bf[3]);
            }
        }

        #pragma unroll
        for (int nt = 0; nt < 8; nt++){
            sacc[nt][0] = exp2f(sacc[nt][0] - CSH); l0 += sacc[nt][0];
            sacc[nt][1] = exp2f(sacc[nt][1] - CSH); l0 += sacc[nt][1];
            sacc[nt][2] = exp2f(sacc[nt][2] - CSH); l1 += sacc[nt][2];
            sacc[nt][3] = exp2f(sacc[nt][3] - CSH); l1 += sacc[nt][3];
        }

        uint32_t pf[4][4];
        #pragma unroll
        for (int kk = 0; kk < 4; kk++){
            PACKBF(pf[kk][0], sacc[2*kk][0],     sacc[2*kk][1]);
            PACKBF(pf[kk][1], sacc[2*kk][2],     sacc[2*kk][3]);
            PACKBF(pf[kk][2], sacc[2*kk + 1][0], sacc[2*kk + 1][1]);
            PACKBF(pf[kk][3], sacc[2*kk + 1][2], sacc[2*kk + 1][3]);
        }

        #pragma unroll
        for (int kk = 0; kk < 4; kk++){
            #pragma unroll
            for (int p = 0; p < 4; p++){
                uint32_t bv[4];
                const int vrow = kk*16 + (grp >> 1)*8 + rin;
                LDSM4T(bv, st + 12288u + (uint32_t)(vrow*128)
                           + (uint32_t)(((2*p + (grp & 1)) ^ (vrow & 7)) << 4));
                MMA16816(oacc[2*p],     pf[kk], bv[0], bv[2]);
                MMA16816(oacc[2*p + 1], pf[kk], bv[1], bv[3]);
            }
        }
        __syncthreads();
        if (it + 2 < SS/64) issueKV(it + 2, st);
    }

    l0 += __shfl_xor_sync(0xffffffffu, l0, 1);
    l0 += __shfl_xor_sync(0xffffffffu, l0, 2);
    l1 += __shfl_xor_sync(0xffffffffu, l1, 1);
    l1 += __shfl_xor_sync(0xffffffffu, l1, 2);
    const float inv0 = 1.f / l0, inv1 = 1.f / l1;
    const int r0g = q0 + wid*16 + (lane >> 2);
    const size_t t0 = (size_t)(b*SS + r0g), t1 = t0 + 8;
    const int cb = h*DHH + 2*(lane & 3);
    #pragma unroll
    for (int j = 0; j < 8; j++){
        const float v0 = oacc[j][0]*inv0, v1 = oacc[j][1]*inv0;
        const float v2 = oacc[j][2]*inv1, v3 = oacc[j][3]*inv1;
        __nv_bfloat162 hp0; hp0.x = __float2bfloat16(v0); hp0.y = __float2bfloat16(v1);
        __nv_bfloat162 hp1; hp1.x = __float2bfloat16(v2); hp1.y = __float2bfloat16(v3);
        *(__nv_bfloat162*)(ah + t0*DD + cb + 8*j) = hp0;
        *(__nv_bfloat162*)(ah + t1*DD + cb + 8*j) = hp1;
    }
}

// ============ aux loss ============
__global__ __launch_bounds__(512) void msum_loss(
    const float* __restrict__ bpart, float* __restrict__ out, int out_idx)
{
    __shared__ float red[512];
    const int tid = threadIdx.x;
    const int h = tid >> 5, n = tid & 31;
    float sq = 0.f, sk = 0.f;
    #pragma unroll 8
    for (int t = 0; t < NT; t++){
        sq += bpart[(((size_t)0*HH + h)*NT + t)*NBB + n];
        sk += bpart[(((size_t)1*HH + h)*NT + t)*NBB + n];
    }
    const float mq = sq * (1.0f/TOK), mk = sk * (1.0f/TOK);
    red[tid] = mq*mq + mk*mk; __syncthreads();
    #pragma unroll
    for (int o = 256; o > 0; o >>= 1) { if (tid < o) red[tid] += red[tid+o]; __syncthreads(); }
    if (tid == 0) out[out_idx] = 0.5f * (float)NBB * red[0] / (float)HH;
}

// ============ host launch ============
extern "C" void kernel_launch(void* const* d_in, const int* in_sizes, int n_in,
                              void* d_out, int out_size)
{
    const float* inputs = (const float*)d_in[0];
    const float* ln1_g  = (const float*)d_in[1];
    const float* ln1_b  = (const float*)d_in[2];
    const float* Wq     = (const float*)d_in[3];
    const float* Wk     = (const float*)d_in[4];
    const float* Wv     = (const float*)d_in[5];
    const float* Whq    = (const float*)d_in[6];
    const float* Whk    = (const float*)d_in[7];
    const float* Wo     = (const float*)d_in[8];
    const float* ln2_g  = (const float*)d_in[9];
    const float* ln2_b  = (const float*)d_in[10];
    const float* W1     = (const float*)d_in[11];
    const float* b1     = (const float*)d_in[12];
    const float* W2     = (const float*)d_in[13];
    const float* b2     = (const float*)d_in[14];
    float* out = (float*)d_out;

    __nv_bfloat16 *p_xh, *p_ah, *p_y, *p_h1;
    __nv_bfloat16 *p_wqkvh, *p_woh, *p_w1, *p_w2;
    __nv_bfloat16 *p_Qa, *p_Ka, *p_Vb, *p_wt;
    float *p_x, *p_bpart;
    cudaGetSymbolAddress((void**)&p_xh, g_xh);
    cudaGetSymbolAddress((void**)&p_ah, g_ah);
    cudaGetSymbolAddress((void**)&p_x, g_x);
    cudaGetSymbolAddress((void**)&p_y, g_y);
    cudaGetSymbolAddress((void**)&p_h1, g_h1);
    cudaGetSymbolAddress((void**)&p_bpart, g_bpart);
    cudaGetSymbolAddress((void**)&p_wqkvh, g_wqkvh);
    cudaGetSymbolAddress((void**)&p_woh, g_woh);
    cudaGetSymbolAddress((void**)&p_w1, g_w1);
    cudaGetSymbolAddress((void**)&p_w2, g_w2);
    cudaGetSymbolAddress((void**)&p_Qa, g_Qa);   cudaGetSymbolAddress((void**)&p_Ka, g_Ka);
    cudaGetSymbolAddress((void**)&p_Vb, g_Vb);   cudaGetSymbolAddress((void**)&p_wt, g_wt);

    cudaFuncSetAttribute((const void*)mma_gemm<4,0>, cudaFuncAttributeMaxDynamicSharedMemorySize, GSM);
    cudaFuncSetAttribute((const void*)mma_gemm<1,0>, cudaFuncAttributeMaxDynamicSharedMemorySize, GSM);
    cudaFuncSetAttribute((const void*)mma_gemm<2,1>, cudaFuncAttributeMaxDynamicSharedMemorySize, GSM);
    cudaFuncSetAttribute((const void*)mma_gemm<3,1>, cudaFuncAttributeMaxDynamicSharedMemorySize, GSM);
    cudaFuncSetAttribute((const void*)flash_mma, cudaFuncAttributeMaxDynamicSharedMemorySize, FSM);
    cudaFuncSetAttribute((const void*)bucket2, cudaFuncAttributeMaxDynamicSharedMemorySize, B2SM);

    ln_split<0><<<TOK, 256>>>(inputs, ln1_g, ln1_b, p_xh);                         // 1
    wprep<<<12288, 256>>>(Wq, Wk, Wv, Wo, W1, W2);                                 // 2
    wtrans<<<dim3(HH,2), 256>>>(Whq, Whk, p_wt);                                   // 3
    mma_gemm<4,0><<<dim3(QKVD/128, TOK/256), 256, GSM>>>(                          // 4: QKV (profiled)
        p_xh, p_wqkvh, nullptr, nullptr, nullptr, p_Qa, p_Ka, p_Vb,
        TOK, QKVD, DD);
    bucket2<<<dim3(HH, NT), 128, B2SM>>>(p_Qa, p_Ka, p_wt, p_bpart, p_Qa, p_Ka);   // 5
    flash_mma<<<dim3(BH, SS/128), 256, FSM>>>(p_Qa, p_Ka, p_Vb, p_ah);             // 6
    mma_gemm<1,0><<<dim3(DD/128, TOK/256), 256, GSM>>>(                            // 7: Wo + residual
        p_ah, p_woh, p_x, nullptr, inputs, nullptr, nullptr, nullptr,
        TOK, DD, DD);
    ln_split<1><<<TOK, 256>>>(p_x, ln2_g, ln2_b, p_y);                             // 8
    mma_gemm<2,1><<<dim3(MLPD/128, TOK/256), 256, GSM>>>(                          // 9: MLP1 fp16
        p_y, p_w1, nullptr, b1, nullptr, p_h1, nullptr, nullptr,
        TOK, MLPD, DD);
    mma_gemm<3,1><<<dim3(DD/128, TOK/256), 256, GSM>>>(                            // 10: MLP2 fp16
        p_h1, p_w2, out, b2, p_x, nullptr, nullptr, nullptr,
        TOK, DD, MLPD);
    msum_loss<<<1, 512>>>(p_bpart, out, out_size - 1);                             // 11
}

// round 15
// speedup vs baseline: 1.1895x; 1.1895x over previous
#include <cuda_runtime.h>
#include <cuda_bf16.h>
#include <cuda_fp16.h>
#include <math.h>
#include <stdint.h>

#define BB   2
#define SS   2048
#define DD   1024
#define HH   16
#define DHH  64
#define NBB  32
#define MLPD 4096
#define TOK  (BB*SS)
#define HN   (HH*NBB)
#define QKVD 3072
#define BH   (BB*HH)
#define NT   (TOK/128)

__device__ __align__(128) __nv_bfloat16 g_xh [TOK*DD];
__device__ __align__(128) __nv_bfloat16 g_ah [TOK*DD];
__device__ __align__(128) float         g_x  [TOK*DD];
__device__ __align__(128) __nv_bfloat16 g_y  [TOK*DD];        // fp16 payload
__device__ __align__(128) __nv_bfloat16 g_h1 [TOK*MLPD];      // fp16 payload
__device__ __align__(128) float         g_bpart[2*HH*NT*NBB];
__device__ __align__(128) __nv_bfloat16 g_wqkvh[QKVD*DD];
__device__ __align__(128) __nv_bfloat16 g_woh [DD*DD];
__device__ __align__(128) __nv_bfloat16 g_w1 [MLPD*DD];       // fp16 payload
__device__ __align__(128) __nv_bfloat16 g_w2 [DD*MLPD];       // fp16 payload
__device__ __align__(128) __nv_bfloat16 g_Qa [BH*SS*96];
__device__ __align__(128) __nv_bfloat16 g_Ka [BH*SS*96];
__device__ __align__(128) __nv_bfloat16 g_Vb [BH*SS*64];
__device__ __align__(128) __nv_bfloat16 g_wt [2*HH*NBB*64];

__device__ __forceinline__ uint32_t smem_u32(const void* p){
    uint32_t a;
    asm("{ .reg .u64 t; cvta.to.shared.u64 t, %1; cvt.u32.u64 %0, t; }" : "=r"(a) : "l"(p));
    return a;
}
#define CPA16(dst, src) \
    asm volatile("cp.async.cg.shared.global [%0], [%1], 16;" :: "r"(dst), "l"(src))
#define CP_COMMIT() asm volatile("cp.async.commit_group;" ::: "memory")
#define CP_WAIT2()  asm volatile("cp.async.wait_group 2;" ::: "memory")
#define CP_WAIT1()  asm volatile("cp.async.wait_group 1;" ::: "memory")
#define CP_WAIT0()  asm volatile("cp.async.wait_group 0;" ::: "memory")
#define LDSM4(r, addr) \
    asm volatile("ldmatrix.sync.aligned.m8n8.x4.shared.b16 {%0,%1,%2,%3}, [%4];" \
        : "=r"((r)[0]), "=r"((r)[1]), "=r"((r)[2]), "=r"((r)[3]) : "r"(addr))
#define LDSM4T(r, addr) \
    asm volatile("ldmatrix.sync.aligned.m8n8.x4.trans.shared.b16 {%0,%1,%2,%3}, [%4];" \
        : "=r"((r)[0]), "=r"((r)[1]), "=r"((r)[2]), "=r"((r)[3]) : "r"(addr))
#define MMA16816(d, a, b0, b1) \
    asm volatile("mma.sync.aligned.m16n8k16.row.col.f32.bf16.bf16.f32 " \
        "{%0,%1,%2,%3}, {%4,%5,%6,%7}, {%8,%9}, {%0,%1,%2,%3};" \
        : "+f"((d)[0]), "+f"((d)[1]), "+f"((d)[2]), "+f"((d)[3]) \
        : "r"((a)[0]), "r"((a)[1]), "r"((a)[2]), "r"((a)[3]), "r"(b0), "r"(b1))
#define MMAH16816(d, a, b0, b1) \
    asm volatile("mma.sync.aligned.m16n8k16.row.col.f32.f16.f16.f32 " \
        "{%0,%1,%2,%3}, {%4,%5,%6,%7}, {%8,%9}, {%0,%1,%2,%3};" \
        : "+f"((d)[0]), "+f"((d)[1]), "+f"((d)[2]), "+f"((d)[3]) \
        : "r"((a)[0]), "r"((a)[1]), "r"((a)[2]), "r"((a)[3]), "r"(b0), "r"(b1))
#define PACKBF(d, lo, hi) \
    asm("cvt.rn.bf16x2.f32 %0, %1, %2;" : "=r"(d) : "f"(hi), "f"(lo))

// ===== mma.sync GEMM: CTA 128x128, warp 64x32, K-chunk 64, 3-stage, occ 2 =====
// EPI: 1 +res fp32 | 2 +bias,relu->fp16 | 3 +bias+res fp32 | 4 qkv->Qa/Ka/Vb
#define SB   32768u
#define GSM  (3*32768)   // 98304 >= epilogue staging 67584

template<int EPI, int F16>
__global__ __launch_bounds__(256, 2) void mma_gemm(
    const __nv_bfloat16* __restrict__ A, const __nv_bfloat16* __restrict__ B,
    float* __restrict__ C, const float* __restrict__ bias, const float* __restrict__ res,
    __nv_bfloat16* __restrict__ Oh, __nv_bfloat16* __restrict__ Ol,
    __nv_bfloat16* __restrict__ Vo,
    int M, int N, int K)
{
    extern __shared__ char sm[];
    const uint32_t smu = smem_u32(sm);
    const int tid = threadIdx.x;
    const int wid = tid >> 5, lane = tid & 31;
    const int bm = blockIdx.y * 128, bn = blockIdx.x * 128;
    const int wm = wid >> 2, wn = wid & 3;

    // producers: 2 threads per row (128 rows), 4x16B each; row = 128 B (64 bf16)
    const int prow = tid >> 1, phalf = tid & 1;
    uint32_t pdA[4];
    #pragma unroll
    for (int j = 0; j < 4; j++)
        pdA[j] = (uint32_t)(prow*128) + ((((uint32_t)(phalf*4 + j)) ^ (uint32_t)(prow & 7)) << 4);
    const __nv_bfloat16* gA = A + (size_t)(bm + prow)*K + phalf*32;
    const __nv_bfloat16* gB = B + (size_t)(bn + prow)*K + phalf*32;

    const int g   = lane >> 3, rin = lane & 7;
    const int roff = (g & 1)*8 + rin;
    const uint32_t chi = (uint32_t)(g >> 1);
    uint32_t aRow[4], aSw[4], bRow[2], bSw[2];
    #pragma unroll
    for (int mi = 0; mi < 4; mi++){
        const int r = wm*64 + mi*16 + roff;
        aRow[mi] = (uint32_t)(r*128); aSw[mi] = (uint32_t)(r & 7);
    }
    #pragma unroll
    for (int nj = 0; nj < 2; nj++){
        const int r = wn*32 + nj*16 + roff;
        bRow[nj] = 16384u + (uint32_t)(r*128); bSw[nj] = (uint32_t)(r & 7);
    }

    float acc[4][4][4];
    #pragma unroll
    for (int mi = 0; mi < 4; mi++)
        #pragma unroll
        for (int nj = 0; nj < 4; nj++)
            #pragma unroll
            for (int e = 0; e < 4; e++) acc[mi][nj][e] = 0.f;

    auto issue = [&](int c, uint32_t st){
        const int kc = c << 6;
        #pragma unroll
        for (int j = 0; j < 4; j++){
            CPA16(st + pdA[j],          gA + kc + j*8);
            CPA16(st + 16384u + pdA[j], gB + kc + j*8);
        }
        CP_COMMIT();
    };

    const int nch = K >> 6;
    issue(0, smu);
    issue(1, smu + SB);

    for (int c = 0; c < nch; c++){
        const uint32_t st = smu + (uint32_t)(c % 3)*SB;
        CP_WAIT1();
        __syncthreads();
        if (c + 2 < nch) issue(c + 2, smu + (uint32_t)((c + 2) % 3)*SB);
        else CP_COMMIT();

        #pragma unroll
        for (int ks = 0; ks < 4; ks++){
            const uint32_t ch = (uint32_t)(ks*2) + chi;
            uint32_t fa[4][4], fb[2][4];
            #pragma unroll
            for (int mi = 0; mi < 4; mi++)
                LDSM4(fa[mi], st + aRow[mi] + ((ch ^ aSw[mi]) << 4));
            #pragma unroll
            for (int nj = 0; nj < 2; nj++)
                LDSM4(fb[nj], st + bRow[nj] + ((ch ^ bSw[nj]) << 4));
            #pragma unroll
            for (int mi = 0; mi < 4; mi++)
                #pragma unroll
                for (int nj = 0; nj < 4; nj++){
                    const int jg = nj >> 1, jl = nj & 1;
                    if (F16) MMAH16816(acc[mi][nj], fa[mi], fb[jg][jl], fb[jg][2 + jl]);
                    else     MMA16816 (acc[mi][nj], fa[mi], fb[jg][jl], fb[jg][2 + jl]);
                }
        }
    }
    CP_WAIT0();
    __syncthreads();

    float* Csm = (float*)sm;
    #pragma unroll
    for (int mi = 0; mi < 4; mi++)
        #pragma unroll
        for (int nj = 0; nj < 4; nj++){
            const int r  = wm*64 + mi*16 + (lane >> 2);
            const int cc = wn*32 + nj*8  + (lane & 3)*2;
            *(float2*)&Csm[r*132 + cc]       = make_float2(acc[mi][nj][0], acc[mi][nj][1]);
            *(float2*)&Csm[(r + 8)*132 + cc] = make_float2(acc[mi][nj][2], acc[mi][nj][3]);
        }
    __syncthreads();

    #pragma unroll 1
    for (int it = 0; it < 16; it++){
        const int i = it*256 + tid;
        const int row = i >> 5;
        const int cq  = (i & 31) << 2;
        const float* cp = Csm + row*132 + cq;
        float a0 = cp[0], a1 = cp[1], a2 = cp[2], a3 = cp[3];
        const size_t gb = (size_t)(bm + row)*N + bn + cq;
        if (EPI == 1){
            const float4 r4 = *(const float4*)(res + gb);
            float4 o = {a0 + r4.x, a1 + r4.y, a2 + r4.z, a3 + r4.w};
            *(float4*)(C + gb) = o;
        } else if (EPI == 2){
            const float4 b4 = *(const float4*)(bias + bn + cq);
            float v0 = fmaxf(a0 + b4.x, 0.f), v1 = fmaxf(a1 + b4.y, 0.f);
            float v2 = fmaxf(a2 + b4.z, 0.f), v3 = fmaxf(a3 + b4.w, 0.f);
            *(__half2*)((__half*)Oh + gb)     = __floats2half2_rn(v0, v1);
            *(__half2*)((__half*)Oh + gb + 2) = __floats2half2_rn(v2, v3);
        } else if (EPI == 3){
            const float4 b4 = *(const float4*)(bias + bn + cq);
            const float4 r4 = *(const float4*)(res + gb);
            float4 o = {a0 + b4.x + r4.x, a1 + b4.y + r4.y,
                        a2 + b4.z + r4.z, a3 + b4.w + r4.w};
            *(float4*)(C + gb) = o;
        } else {
            const int col = bn + cq;
            const int sel = col >> 10;
            const int h   = (col & 1023) >> 6;
            const int d   = col & 63;
            const int tv  = bm + row;
            const size_t bhs = ((size_t)(((tv >> 11)*HH) + h)*SS + (tv & 2047));
            const float QSC = 0.125f * 1.44269504088896340736f;
            if (sel == 0){
                __nv_bfloat162 o0; o0.x = __float2bfloat16(a0*QSC); o0.y = __float2bfloat16(a1*QSC);
                __nv_bfloat162 o1; o1.x = __float2bfloat16(a2*QSC); o1.y = __float2bfloat16(a3*QSC);
                *(__nv_bfloat162*)(Oh + bhs*96 + d)     = o0;
                *(__nv_bfloat162*)(Oh + bhs*96 + d + 2) = o1;
            } else if (sel == 1){
                __nv_bfloat162 o0; o0.x = __float2bfloat16(a0); o0.y = __float2bfloat16(a1);
                __nv_bfloat162 o1; o1.x = __float2bfloat16(a2); o1.y = __float2bfloat16(a3);
                *(__nv_bfloat162*)(Ol + bhs*96 + d)     = o0;
                *(__nv_bfloat162*)(Ol + bhs*96 + d + 2) = o1;
            } else {
                __nv_bfloat162 o0; o0.x = __float2bfloat16(a0); o0.y = __float2bfloat16(a1);
                __nv_bfloat162 o1; o1.x = __float2bfloat16(a2); o1.y = __float2bfloat16(a3);
                *(__nv_bfloat162*)(Vo + bhs*64 + d)     = o0;
                *(__nv_bfloat162*)(Vo + bhs*64 + d + 2) = o1;
            }
        }
    }
}

// ============ unified weight prep ============
__global__ __launch_bounds__(256) void wprep(
    const float* __restrict__ Wq, const float* __restrict__ Wk,
    const float* __restrict__ Wv, const float* __restrict__ Wo,
    const float* __restrict__ W1, const float* __restrict__ W2)
{
    __shared__ float t[32][33];
    const int id = blockIdx.x;
    const float* W; __nv_bfloat16* T; int K, N, bx, by, f16;
    if (id < 4096){
        const int s = id >> 10, r = id & 1023;
        if (s < 3){ W = s == 0 ? Wq : (s == 1 ? Wk : Wv); T = g_wqkvh + (size_t)s*DD*DD; }
        else      { W = Wo; T = g_woh; }
        K = DD; N = DD; bx = r & 31; by = r >> 5; f16 = 0;
    } else if (id < 8192){
        const int r = id - 4096; W = W1; T = g_w1; K = DD; N = MLPD;
        bx = r & 127; by = r >> 7; f16 = 1;
    } else {
        const int r = id - 8192; W = W2; T = g_w2; K = MLPD; N = DD;
        bx = r & 31; by = r >> 5; f16 = 1;
    }
    const int tx = threadIdx.x & 31, ty = threadIdx.x >> 5;
    const int k0 = by*32, n0 = bx*32;
    #pragma unroll
    for (int i = 0; i < 4; i++)
        t[ty + i*8][tx] = W[(size_t)(k0 + ty + i*8)*N + n0 + tx];
    __syncthreads();
    #pragma unroll
    for (int i = 0; i < 4; i++){
        const int n = n0 + ty + i*8;
        const float x = t[tx][ty + i*8];
        if (f16) ((__half*)T)[(size_t)n*K + k0 + tx] = __float2half(x);
        else     T[(size_t)n*K + k0 + tx] = __float2bfloat16(x);
    }
}

__global__ __launch_bounds__(256) void wtrans(
    const float* __restrict__ Whq, const float* __restrict__ Whk,
    __nv_bfloat16* __restrict__ WT)
{
    const int h = blockIdx.x, m = blockIdx.y;
    const float* src = m ? Whk : Whq;
    const float sc = m ? 1.f : (1.f/(0.125f*1.44269504088896340736f));
    for (int i = threadIdx.x; i < DHH*NBB; i += 256){
        const int f = i >> 5, n = i & 31;
        WT[(((size_t)m*HH + h)*NBB + n)*64 + f] =
            __float2bfloat16(src[((size_t)h*DHH + f)*NBB + n]*sc);
    }
}

// ============ LayerNorm: MODE 0 = bf16 out, 1 = fp16 out ============
template<int MODE>
__global__ __launch_bounds__(256) void ln_split(
    const float* __restrict__ in, const float* __restrict__ g,
    const float* __restrict__ bta, __nv_bfloat16* __restrict__ oh)
{
    __shared__ float red[256];
    const int t = blockIdx.x, tid = threadIdx.x;
    const float4 x = ((const float4*)(in + (size_t)t*DD))[tid];

    float sum = x.x + x.y + x.z + x.w;
    red[tid] = sum; __syncthreads();
    #pragma unroll
    for (int o = 128; o > 0; o >>= 1) { if (tid < o) red[tid] += red[tid+o]; __syncthreads(); }
    const float mu = red[0] * (1.0f/DD);
    __syncthreads();

    float d0 = x.x-mu, d1 = x.y-mu, d2 = x.z-mu, d3 = x.w-mu;
    red[tid] = d0*d0 + d1*d1 + d2*d2 + d3*d3; __syncthreads();
    #pragma unroll
    for (int o = 128; o > 0; o >>= 1) { if (tid < o) red[tid] += red[tid+o]; __syncthreads(); }
    const float rs = rsqrtf(red[0]*(1.0f/DD) + 1e-6f);

    const float4 gg = ((const float4*)g)[tid];
    const float4 bb = ((const float4*)bta)[tid];
    float y0 = d0*rs*gg.x + bb.x, y1 = d1*rs*gg.y + bb.y;
    float y2 = d2*rs*gg.z + bb.z, y3 = d3*rs*gg.w + bb.w;

    if (MODE == 0){
        __nv_bfloat162 hp0; hp0.x = __float2bfloat16(y0); hp0.y = __float2bfloat16(y1);
        __nv_bfloat162 hp1; hp1.x = __float2bfloat16(y2); hp1.y = __float2bfloat16(y3);
        __nv_bfloat162* ph = (__nv_bfloat162*)(oh + (size_t)t*DD);
        ph[tid*2] = hp0; ph[tid*2 + 1] = hp1;
    } else {
        __half2* ph = (__half2*)((__half*)oh + (size_t)t*DD);
        ph[tid*2]     = __floats2half2_rn(y0, y1);
        ph[tid*2 + 1] = __floats2half2_rn(y2, y3);
    }
}

// ============ bucket softmax via mma (static shift) + fused partial sums ============
#define B2SM 41472
__global__ __launch_bounds__(128) void bucket2(
    const __nv_bfloat16* __restrict__ Qa, const __nv_bfloat16* __restrict__ Ka,
    const __nv_bfloat16* __restrict__ WT, float* __restrict__ bpart,
    __nv_bfloat16* __restrict__ Qao, __nv_bfloat16* __restrict__ Kao)
{
    extern __shared__ char sm[];
    const uint32_t smu = smem_u32(sm);
    const int tid = threadIdx.x, wid = tid >> 5, lane = tid & 31;
    const int h = blockIdx.x;
    const int ty = blockIdx.y, bq = ty >> 4, sbase = (ty & 15)*128;
    const int bh = bq*HH + h;
    const uint32_t Qs = smu, Ks = smu + 16384u, Ws = smu + 32768u;
    float* csum = (float*)(sm + 40960);

    const size_t qa0 = ((size_t)bh*SS + sbase)*96;
    for (int i = tid; i < 128*8; i += 128){
        const int r = i >> 3, c = i & 7;
        const uint32_t off = (uint32_t)(r*128) + (uint32_t)((c ^ (r & 7)) << 4);
        CPA16(Qs + off, (const char*)(Qa + qa0 + (size_t)r*96 + c*8));
        CPA16(Ks + off, (const char*)(Ka + qa0 + (size_t)r*96 + c*8));
    }
    for (int i = tid; i < 2*32*8; i += 128){
        const int m = i >> 8, r = (i >> 3) & 31, c = i & 7;
        CPA16(Ws + (uint32_t)(m*4096) + (uint32_t)(r*128) + (uint32_t)((c ^ (r & 7)) << 4),
              (const char*)(WT + ((size_t)m*HH + h)*NBB*64 + (size_t)r*64 + c*8));
    }
    CP_COMMIT(); CP_WAIT0(); __syncthreads();

    const int grp = lane >> 3, rin = lane & 7;
    const int roff = (grp & 1)*8 + rin, chi = grp >> 1;
    const float BSC = 0.1f * 1.44269504088896340736f;

    #pragma unroll
    for (int m = 0; m < 2; m++){
        const uint32_t As = m ? Ks : Qs;
        const uint32_t Bs = Ws + (uint32_t)m*4096u;
        float acc[2][4][4];
        #pragma unroll
        for (int mi = 0; mi < 2; mi++)
            #pragma unroll
            for (int nj = 0; nj < 4; nj++)
                #pragma unroll
                for (int e = 0; e < 4; e++) acc[mi][nj][e] = 0.f;

        #pragma unroll
        for (int ks = 0; ks < 4; ks++){
            uint32_t fa[2][4], fb0[4], fb1[4];
            #pragma unroll
            for (int mi = 0; mi < 2; mi++){
                const int r = wid*32 + mi*16 + roff;
                LDSM4(fa[mi], As + (uint32_t)(r*128) + (uint32_t)(((2*ks + chi) ^ (r & 7)) << 4));
            }
            { const int r = roff;      LDSM4(fb0, Bs + (uint32_t)(r*128) + (uint32_t)(((2*ks + chi) ^ (r & 7)) << 4)); }
            { const int r = 16 + roff; LDSM4(fb1, Bs + (uint32_t)(r*128) + (uint32_t)(((2*ks + chi) ^ (r & 7)) << 4)); }
            #pragma unroll
            for (int mi = 0; mi < 2; mi++){
                MMA16816(acc[mi][0], fa[mi], fb0[0], fb0[2]);
                MMA16816(acc[mi][1], fa[mi], fb0[1], fb0[3]);
                MMA16816(acc[mi][2], fa[mi], fb1[0], fb1[2]);
                MMA16816(acc[mi][3], fa[mi], fb1[1], fb1[3]);
            }
        }

        float local8[8];
        #pragma unroll
        for (int e = 0; e < 8; e++) local8[e] = 0.f;

        #pragma unroll
        for (int mi = 0; mi < 2; mi++){
            float s0v = 0.f, s1v = 0.f;
            #pragma unroll
            for (int nj = 0; nj < 4; nj++){
                acc[mi][nj][0] = __expf(acc[mi][nj][0]); s0v += acc[mi][nj][0];
                acc[mi][nj][1] = __expf(acc[mi][nj][1]); s0v += acc[mi][nj][1];
                acc[mi][nj][2] = __expf(acc[mi][nj][2]); s1v += acc[mi][nj][2];
                acc[mi][nj][3] = __expf(acc[mi][nj][3]); s1v += acc[mi][nj][3];
            }
            s0v += __shfl_xor_sync(~0u, s0v, 1); s0v += __shfl_xor_sync(~0u, s0v, 2);
            s1v += __shfl_xor_sync(~0u, s1v, 1); s1v += __shfl_xor_sync(~0u, s1v, 2);
            const float i0 = 1.f/s0v, i1 = 1.f/s1v;
            const int r_lo = wid*32 + mi*16 + (lane >> 2);
            const int srow0 = sbase + r_lo, srow1 = srow0 + 8;
            __nv_bfloat16* oo = m ? Kao : Qao;
            const float sc = m ? 1.f : BSC;
            #pragma unroll
            for (int nj = 0; nj < 4; nj++){
                const int cc = nj*8 + (lane & 3)*2;
                float p0 = acc[mi][nj][0]*i0, p1 = acc[mi][nj][1]*i0;
                float p2 = acc[mi][nj][2]*i1, p3 = acc[mi][nj][3]*i1;
                local8[nj*2]     += p0 + p2;
                local8[nj*2 + 1] += p1 + p3;
                __nv_bfloat162 o0; o0.x = __float2bfloat16(p0*sc); o0.y = __float2bfloat16(p1*sc);
                __nv_bfloat162 o1; o1.x = __float2bfloat16(p2*sc); o1.y = __float2bfloat16(p3*sc);
                *(__nv_bfloat162*)(oo + ((size_t)bh*SS + srow0)*96 + 64 + cc) = o0;
                *(__nv_bfloat162*)(oo + ((size_t)bh*SS + srow1)*96 + 64 + cc) = o1;
            }
        }

        #pragma unroll
        for (int e = 0; e < 8; e++){
            local8[e] += __shfl_down_sync(~0u, local8[e], 16);
            local8[e] += __shfl_down_sync(~0u, local8[e], 8);
            local8[e] += __shfl_down_sync(~0u, local8[e], 4);
        }
        if ((lane >> 2) == 0){
            #pragma unroll
            for (int nj = 0; nj < 4; nj++){
                csum[wid*32 + nj*8 + lane*2]     = local8[nj*2];
                csum[wid*32 + nj*8 + lane*2 + 1] = local8[nj*2 + 1];
            }
        }
        __syncthreads();
        if (tid < 32){
            const float v = csum[tid] + csum[32 + tid] + csum[64 + tid] + csum[96 + tid];
            bpart[(((size_t)m*HH + h)*NT + ty)*NBB + tid] = v;
        }
        __syncthreads();
    }
}

// ============ flash attention: static-shift softmax ============
#define FSM 65536
#define CSH 24.0f
__global__ __launch_bounds__(256, 2) void flash_mma(
    const __nv_bfloat16* __restrict__ Qa, const __nv_bfloat16* __restrict__ Ka,
    const __nv_bfloat16* __restrict__ Vb, __nv_bfloat16* __restrict__ ah)
{
    extern __shared__ char sm[];
    const uint32_t smu = smem_u32(sm);
    const int tid = threadIdx.x, wid = tid >> 5, lane = tid & 31;
    const int bh = blockIdx.x, b = bh >> 4, h = bh & 15;
    const int q0 = blockIdx.y * 128;

    const uint32_t QC = smu, QB = smu + 16384u;
    const uint32_t ST0 = smu + 24576u;

    {
        const size_t qb0 = ((size_t)bh*SS + q0)*96;
        #pragma unroll
        for (int i = 0; i < 4; i++){
            const int q = tid + i*256, r = q >> 3, c = q & 7;
            CPA16(QC + (uint32_t)(r*128) + (uint32_t)(((c ^ (r & 7)) << 4)),
                  (const char*)(Qa + qb0 + (size_t)r*96 + c*8));
        }
        #pragma unroll
        for (int i = 0; i < 2; i++){
            const int q = tid + i*256, r = q >> 2, c = q & 3;
            CPA16(QB + (uint32_t)(r*64) + (uint32_t)(((c ^ ((r >> 1) & 3)) << 4)),
                  (const char*)(Qa + qb0 + (size_t)r*96 + 64 + c*8));
        }
        CP_COMMIT();
    }
    auto issueKV = [&](int it, uint32_t st){
        const size_t kb0 = ((size_t)bh*SS + it*64)*96;
        const size_t vb0 = ((size_t)bh*SS + it*64)*64;
        #pragma unroll
        for (int i = 0; i < 2; i++){
            const int q = tid + i*256, r = q >> 3, c = q & 7;
            CPA16(st + (uint32_t)(r*128) + (uint32_t)((c ^ (r & 7)) << 4),
                  (const char*)(Ka + kb0 + (size_t)r*96 + c*8));
        }
        {
            const int r = tid >> 2, c = tid & 3;
            CPA16(st + 8192u + (uint32_t)(r*64) + (uint32_t)((c ^ ((r >> 1) & 3)) << 4),
                  (const char*)(Ka + kb0 + (size_t)r*96 + 64 + c*8));
        }
        #pragma unroll
        for (int i = 0; i < 2; i++){
            const int q = tid + i*256, r = q >> 3, c = q & 7;
            CPA16(st + 12288u + (uint32_t)(r*128) + (uint32_t)((c ^ (r & 7)) << 4),
                  (const char*)(Vb + vb0 + (size_t)r*64 + c*8));
        }
        CP_COMMIT();
    };
    issueKV(0, ST0);
    issueKV(1, ST0 + 20480u);

    CP_WAIT2();
    __syncthreads();

    const int grp = lane >> 3, rin = lane & 7;
    const int roff = (grp & 1)*8 + rin, chi = grp >> 1;

    uint32_t qf[6][4];
    {
        const int r = wid*16 + roff;
        #pragma unroll
        for (int ks = 0; ks < 4; ks++)
            LDSM4(qf[ks], QC + (uint32_t)(r*128) + (uint32_t)(((2*ks + chi) ^ (r & 7)) << 4));
        #pragma unroll
        for (int ks = 0; ks < 2; ks++)
            LDSM4(qf[4 + ks], QB + (uint32_t)(r*64) + (uint32_t)(((2*ks + chi) ^ ((r >> 1) & 3)) << 4));
    }

    float oacc[8][4];
    #pragma unroll
    for (int nt = 0; nt < 8; nt++)
        #pragma unroll
        for (int e = 0; e < 4; e++) oacc[nt][e] = 0.f;
    float l0 = 0.f, l1 = 0.f;

    for (int it = 0; it < SS/64; it++){
        const uint32_t st = ST0 + (uint32_t)(it & 1)*20480u;
        if (it + 1 < SS/64) CP_WAIT1(); else CP_WAIT0();
        __syncthreads();

        float sacc[8][4];
        #pragma unroll
        for (int nt = 0; nt < 8; nt++)
            #pragma unroll
            for (int e = 0; e < 4; e++) sacc[nt][e] = 0.f;

        #pragma unroll
        for (int ks = 0; ks < 6; ks++){
            #pragma unroll
            for (int p = 0; p < 4; p++){
                uint32_t bf[4];
                const int r = p*16 + roff;
                if (ks < 4)
                    LDSM4(bf, st + (uint32_t)(r*128) + (uint32_t)(((2*ks + chi) ^ (r & 7)) << 4));
                else
                    LDSM4(bf, st + 8192u + (uint32_t)(r*64) + (uint32_t)(((2*(ks-4) + chi) ^ ((r >> 1) & 3)) << 4));
                MMA16816(sacc[2*p],     qf[ks], bf[0], bf[2]);
                MMA16816(sacc[2*p + 1], qf[ks], bf[1], bf[3]);
            }
        }

        #pragma unroll
        for (int nt = 0; nt < 8; nt++){
            sacc[nt][0] = exp2f(sacc[nt][0] - CSH); l0 += sacc[nt][0];
            sacc[nt][1] = exp2f(sacc[nt][1] - CSH); l0 += sacc[nt][1];
            sacc[nt][2] = exp2f(sacc[nt][2] - CSH); l1 += sacc[nt][2];
            sacc[nt][3] = exp2f(sacc[nt][3] - CSH); l1 += sacc[nt][3];
        }

        uint32_t pf[4][4];
        #pragma unroll
        for (int kk = 0; kk < 4; kk++){
            PACKBF(pf[kk][0], sacc[2*kk][0],     sacc[2*kk][1]);
            PACKBF(pf[kk][1], sacc[2*kk][2],     sacc[2*kk][3]);
            PACKBF(pf[kk][2], sacc[2*kk + 1][0], sacc[2*kk + 1][1]);
            PACKBF(pf[kk][3], sacc[2*kk + 1][2], sacc[2*kk + 1][3]);
        }

        #pragma unroll
        for (int kk = 0; kk < 4; kk++){
            #pragma unroll
            for (int p = 0; p < 4; p++){
                uint32_t bv[4];
                const int vrow = kk*16 + (grp >> 1)*8 + rin;
                LDSM4T(bv, st + 12288u + (uint32_t)(vrow*128)
                           + (uint32_t)(((2*p + (grp & 1)) ^ (vrow & 7)) << 4));
                MMA16816(oacc[2*p],     pf[kk], bv[0], bv[2]);
                MMA16816(oacc[2*p + 1], pf[kk], bv[1], bv[3]);
            }
        }
        __syncthreads();
        if (it + 2 < SS/64) issueKV(it + 2, st);
    }

    l0 += __shfl_xor_sync(0xffffffffu, l0, 1);
    l0 += __shfl_xor_sync(0xffffffffu, l0, 2);
    l1 += __shfl_xor_sync(0xffffffffu, l1, 1);
    l1 += __shfl_xor_sync(0xffffffffu, l1, 2);
    const float inv0 = 1.f / l0, inv1 = 1.f / l1;
    const int r0g = q0 + wid*16 + (lane >> 2);
    const size_t t0 = (size_t)(b*SS + r0g), t1 = t0 + 8;
    const int cb = h*DHH + 2*(lane & 3);
    #pragma unroll
    for (int j = 0; j < 8; j++){
        const float v0 = oacc[j][0]*inv0, v1 = oacc[j][1]*inv0;
        const float v2 = oacc[j][2]*inv1, v3 = oacc[j][3]*inv1;
        __nv_bfloat162 hp0; hp0.x = __float2bfloat16(v0); hp0.y = __float2bfloat16(v1);
        __nv_bfloat162 hp1; hp1.x = __float2bfloat16(v2); hp1.y = __float2bfloat16(v3);
        *(__nv_bfloat162*)(ah + t0*DD + cb + 8*j) = hp0;
        *(__nv_bfloat162*)(ah + t1*DD + cb + 8*j) = hp1;
    }
}

// ============ aux loss ============
__global__ __launch_bounds__(512) void msum_loss(
    const float* __restrict__ bpart, float* __restrict__ out, int out_idx)
{
    __shared__ float red[512];
    const int tid = threadIdx.x;
    const int h = tid >> 5, n = tid & 31;
    float sq = 0.f, sk = 0.f;
    #pragma unroll 8
    for (int t = 0; t < NT; t++){
        sq += bpart[(((size_t)0*HH + h)*NT + t)*NBB + n];
        sk += bpart[(((size_t)1*HH + h)*NT + t)*NBB + n];
    }
    const float mq = sq * (1.0f/TOK), mk = sk * (1.0f/TOK);
    red[tid] = mq*mq + mk*mk; __syncthreads();
    #pragma unroll
    for (int o = 256; o > 0; o >>= 1) { if (tid < o) red[tid] += red[tid+o]; __syncthreads(); }
    if (tid == 0) out[out_idx] = 0.5f * (float)NBB * red[0] / (float)HH;
}

// ============ host launch ============
extern "C" void kernel_launch(void* const* d_in, const int* in_sizes, int n_in,
                              void* d_out, int out_size)
{
    const float* inputs = (const float*)d_in[0];
    const float* ln1_g  = (const float*)d_in[1];
    const float* ln1_b  = (const float*)d_in[2];
    const float* Wq     = (const float*)d_in[3];
    const float* Wk     = (const float*)d_in[4];
    const float* Wv     = (const float*)d_in[5];
    const float* Whq    = (const float*)d_in[6];
    const float* Whk    = (const float*)d_in[7];
    const float* Wo     = (const float*)d_in[8];
    const float* ln2_g  = (const float*)d_in[9];
    const float* ln2_b  = (const float*)d_in[10];
    const float* W1     = (const float*)d_in[11];
    const float* b1     = (const float*)d_in[12];
    const float* W2     = (const float*)d_in[13];
    const float* b2     = (const float*)d_in[14];
    float* out = (float*)d_out;

    __nv_bfloat16 *p_xh, *p_ah, *p_y, *p_h1;
    __nv_bfloat16 *p_wqkvh, *p_woh, *p_w1, *p_w2;
    __nv_bfloat16 *p_Qa, *p_Ka, *p_Vb, *p_wt;
    float *p_x, *p_bpart;
    cudaGetSymbolAddress((void**)&p_xh, g_xh);
    cudaGetSymbolAddress((void**)&p_ah, g_ah);
    cudaGetSymbolAddress((void**)&p_x, g_x);
    cudaGetSymbolAddress((void**)&p_y, g_y);
    cudaGetSymbolAddress((void**)&p_h1, g_h1);
    cudaGetSymbolAddress((void**)&p_bpart, g_bpart);
    cudaGetSymbolAddress((void**)&p_wqkvh, g_wqkvh);
    cudaGetSymbolAddress((void**)&p_woh, g_woh);
    cudaGetSymbolAddress((void**)&p_w1, g_w1);
    cudaGetSymbolAddress((void**)&p_w2, g_w2);
    cudaGetSymbolAddress((void**)&p_Qa, g_Qa);   cudaGetSymbolAddress((void**)&p_Ka, g_Ka);
    cudaGetSymbolAddress((void**)&p_Vb, g_Vb);   cudaGetSymbolAddress((void**)&p_wt, g_wt);

    cudaFuncSetAttribute((const void*)mma_gemm<4,0>, cudaFuncAttributeMaxDynamicSharedMemorySize, GSM);
    cudaFuncSetAttribute((const void*)mma_gemm<1,0>, cudaFuncAttributeMaxDynamicSharedMemorySize, GSM);
    cudaFuncSetAttribute((const void*)mma_gemm<2,1>, cudaFuncAttributeMaxDynamicSharedMemorySize, GSM);
    cudaFuncSetAttribute((const void*)mma_gemm<3,1>, cudaFuncAttributeMaxDynamicSharedMemorySize, GSM);
    cudaFuncSetAttribute((const void*)flash_mma, cudaFuncAttributeMaxDynamicSharedMemorySize, FSM);
    cudaFuncSetAttribute((const void*)bucket2, cudaFuncAttributeMaxDynamicSharedMemorySize, B2SM);

    ln_split<0><<<TOK, 256>>>(inputs, ln1_g, ln1_b, p_xh);                         // 1
    wprep<<<12288, 256>>>(Wq, Wk, Wv, Wo, W1, W2);                                 // 2
    wtrans<<<dim3(HH,2), 256>>>(Whq, Whk, p_wt);                                   // 3
    mma_gemm<4,0><<<dim3(QKVD/128, TOK/128), 256, GSM>>>(                          // 4: QKV (profiled)
        p_xh, p_wqkvh, nullptr, nullptr, nullptr, p_Qa, p_Ka, p_Vb,
        TOK, QKVD, DD);
    bucket2<<<dim3(HH, NT), 128, B2SM>>>(p_Qa, p_Ka, p_wt, p_bpart, p_Qa, p_Ka);   // 5
    flash_mma<<<dim3(BH, SS/128), 256, FSM>>>(p_Qa, p_Ka, p_Vb, p_ah);             // 6
    mma_gemm<1,0><<<dim3(DD/128, TOK/128), 256, GSM>>>(                            // 7: Wo + residual
        p_ah, p_woh, p_x, nullptr, inputs, nullptr, nullptr, nullptr,
        TOK, DD, DD);
    ln_split<1><<<TOK, 256>>>(p_x, ln2_g, ln2_b, p_y);                             // 8
    mma_gemm<2,1><<<dim3(MLPD/128, TOK/128), 256, GSM>>>(                          // 9: MLP1 fp16
        p_y, p_w1, nullptr, b1, nullptr, p_h1, nullptr, nullptr,
        TOK, MLPD, DD);
    mma_gemm<3,1><<<dim3(DD/128, TOK/128), 256, GSM>>>(                            // 10: MLP2 fp16
        p_h1, p_w2, out, b2, p_x, nullptr, nullptr, nullptr,
        TOK, DD, MLPD);
    msum_loss<<<1, 512>>>(p_bpart, out, out_size - 1);                             // 11
}

// round 16
// speedup vs baseline: 1.1978x; 1.0069x over previous
#include <cuda_runtime.h>
#include <cuda_bf16.h>
#include <cuda_fp16.h>
#include <math.h>
#include <stdint.h>

#define BB   2
#define SS   2048
#define DD   1024
#define HH   16
#define DHH  64
#define NBB  32
#define MLPD 4096
#define TOK  (BB*SS)
#define HN   (HH*NBB)
#define QKVD 3072
#define BH   (BB*HH)
#define NT   (TOK/128)
#define PGRID 296

__device__ __align__(128) __nv_bfloat16 g_xh [TOK*DD];
__device__ __align__(128) __nv_bfloat16 g_ah [TOK*DD];
__device__ __align__(128) float         g_x  [TOK*DD];
__device__ __align__(128) __nv_bfloat16 g_y  [TOK*DD];        // fp16 payload
__device__ __align__(128) __nv_bfloat16 g_h1 [TOK*MLPD];      // fp16 payload
__device__ __align__(128) float         g_bpart[2*HH*NT*NBB];
__device__ __align__(128) __nv_bfloat16 g_wqkvh[QKVD*DD];
__device__ __align__(128) __nv_bfloat16 g_woh [DD*DD];
__device__ __align__(128) __nv_bfloat16 g_w1 [MLPD*DD];       // fp16 payload
__device__ __align__(128) __nv_bfloat16 g_w2 [DD*MLPD];       // fp16 payload
__device__ __align__(128) __nv_bfloat16 g_Qa [BH*SS*96];
__device__ __align__(128) __nv_bfloat16 g_Ka [BH*SS*96];
__device__ __align__(128) __nv_bfloat16 g_Vb [BH*SS*64];
__device__ __align__(128) __nv_bfloat16 g_wt [2*HH*NBB*64];

__device__ __forceinline__ uint32_t smem_u32(const void* p){
    uint32_t a;
    asm("{ .reg .u64 t; cvta.to.shared.u64 t, %1; cvt.u32.u64 %0, t; }" : "=r"(a) : "l"(p));
    return a;
}
#define CPA16(dst, src) \
    asm volatile("cp.async.cg.shared.global [%0], [%1], 16;" :: "r"(dst), "l"(src))
#define CP_COMMIT() asm volatile("cp.async.commit_group;" ::: "memory")
#define CP_WAIT2()  asm volatile("cp.async.wait_group 2;" ::: "memory")
#define CP_WAIT1()  asm volatile("cp.async.wait_group 1;" ::: "memory")
#define CP_WAIT0()  asm volatile("cp.async.wait_group 0;" ::: "memory")
#define LDSM4(r, addr) \
    asm volatile("ldmatrix.sync.aligned.m8n8.x4.shared.b16 {%0,%1,%2,%3}, [%4];" \
        : "=r"((r)[0]), "=r"((r)[1]), "=r"((r)[2]), "=r"((r)[3]) : "r"(addr))
#define LDSM4T(r, addr) \
    asm volatile("ldmatrix.sync.aligned.m8n8.x4.trans.shared.b16 {%0,%1,%2,%3}, [%4];" \
        : "=r"((r)[0]), "=r"((r)[1]), "=r"((r)[2]), "=r"((r)[3]) : "r"(addr))
#define MMA16816(d, a, b0, b1) \
    asm volatile("mma.sync.aligned.m16n8k16.row.col.f32.bf16.bf16.f32 " \
        "{%0,%1,%2,%3}, {%4,%5,%6,%7}, {%8,%9}, {%0,%1,%2,%3};" \
        : "+f"((d)[0]), "+f"((d)[1]), "+f"((d)[2]), "+f"((d)[3]) \
        : "r"((a)[0]), "r"((a)[1]), "r"((a)[2]), "r"((a)[3]), "r"(b0), "r"(b1))
#define MMAH16816(d, a, b0, b1) \
    asm volatile("mma.sync.aligned.m16n8k16.row.col.f32.f16.f16.f32 " \
        "{%0,%1,%2,%3}, {%4,%5,%6,%7}, {%8,%9}, {%0,%1,%2,%3};" \
        : "+f"((d)[0]), "+f"((d)[1]), "+f"((d)[2]), "+f"((d)[3]) \
        : "r"((a)[0]), "r"((a)[1]), "r"((a)[2]), "r"((a)[3]), "r"(b0), "r"(b1))
#define PACKBF(d, lo, hi) \
    asm("cvt.rn.bf16x2.f32 %0, %1, %2;" : "=r"(d) : "f"(hi), "f"(lo))

// ===== persistent mma.sync GEMM: CTA 128x128, warp 64x32, K-chunk 32, 4-stage, occ 2 =====
// EPI: 1 +res fp32 | 2 +bias,relu->fp16 | 3 +bias+res fp32 | 4 qkv->Qa/Ka/Vb
#define SBQ  16384u
#define GSM  (128*132*4)

template<int EPI, int F16>
__global__ __launch_bounds__(256, 2) void mma_gemm(
    const __nv_bfloat16* __restrict__ A, const __nv_bfloat16* __restrict__ B,
    float* __restrict__ C, const float* __restrict__ bias, const float* __restrict__ res,
    __nv_bfloat16* __restrict__ Oh, __nv_bfloat16* __restrict__ Ol,
    __nv_bfloat16* __restrict__ Vo,
    int M, int N, int K)
{
    extern __shared__ char sm[];
    const uint32_t smu = smem_u32(sm);
    const int tid = threadIdx.x;
    const int wid = tid >> 5, lane = tid & 31;
    const int wm = wid >> 2, wn = wid & 3;
    const int ntx = N >> 7, ntiles = ntx * (M >> 7);

    const int prow = tid >> 1, phalf = tid & 1;
    const uint32_t psw = (uint32_t)((prow >> 1) & 3);
    const uint32_t pd0 = (uint32_t)(prow*64) + ((((uint32_t)phalf*2u + 0u) ^ psw) << 4);
    const uint32_t pd1 = (uint32_t)(prow*64) + ((((uint32_t)phalf*2u + 1u) ^ psw) << 4);

    const int g   = lane >> 3, rin = lane & 7;
    const int roff = (g & 1)*8 + rin;
    const uint32_t chi = (uint32_t)(g >> 1);
    uint32_t aRow[4], aSw[4], bRow[2], bSw[2];
    #pragma unroll
    for (int mi = 0; mi < 4; mi++){
        const int r = wm*64 + mi*16 + roff;
        aRow[mi] = (uint32_t)(r*64); aSw[mi] = (uint32_t)((r >> 1) & 3);
    }
    #pragma unroll
    for (int nj = 0; nj < 2; nj++){
        const int r = wn*32 + nj*16 + roff;
        bRow[nj] = (uint32_t)(r*64); bSw[nj] = (uint32_t)((r >> 1) & 3);
    }
    const int nch = K >> 5;

    for (int t = blockIdx.x; t < ntiles; t += gridDim.x){
        const int bm = (t / ntx) << 7, bn = (t % ntx) << 7;
        const __nv_bfloat16* gA = A + (size_t)(bm + prow)*K + phalf*16;
        const __nv_bfloat16* gB = B + (size_t)(bn + prow)*K + phalf*16;

        float acc[4][4][4];
        #pragma unroll
        for (int mi = 0; mi < 4; mi++)
            #pragma unroll
            for (int nj = 0; nj < 4; nj++)
                #pragma unroll
                for (int e = 0; e < 4; e++) acc[mi][nj][e] = 0.f;

        auto issue = [&](int c, uint32_t st){
            const int kc = c << 5;
            CPA16(st + pd0, gA + kc); CPA16(st + pd1, gA + kc + 8);
            CPA16(st + 8192u + pd0, gB + kc); CPA16(st + 8192u + pd1, gB + kc + 8);
            CP_COMMIT();
        };

        __syncthreads();   // protect Csm (prev tile epilogue) before stage writes
        issue(0, smu);
        issue(1, smu + SBQ);
        issue(2, smu + 2u*SBQ);

        for (int c = 0; c < nch; c++){
            const uint32_t st = smu + (uint32_t)(c & 3)*SBQ;
            CP_WAIT2();
            __syncthreads();
            if (c + 3 < nch) issue(c + 3, smu + (uint32_t)((c + 3) & 3)*SBQ);
            else CP_COMMIT();

            #pragma unroll
            for (int ks = 0; ks < 2; ks++){
                const uint32_t ch = (uint32_t)(ks*2) + chi;
                uint32_t fa[4][4], fb[2][4];
                #pragma unroll
                for (int mi = 0; mi < 4; mi++)
                    LDSM4(fa[mi], st + aRow[mi] + ((ch ^ aSw[mi]) << 4));
                #pragma unroll
                for (int nj = 0; nj < 2; nj++)
                    LDSM4(fb[nj], st + 8192u + bRow[nj] + ((ch ^ bSw[nj]) << 4));
                #pragma unroll
                for (int mi = 0; mi < 4; mi++)
                    #pragma unroll
                    for (int nj = 0; nj < 4; nj++){
                        const int jg = nj >> 1, jl = nj & 1;
                        if (F16) MMAH16816(acc[mi][nj], fa[mi], fb[jg][jl], fb[jg][2 + jl]);
                        else     MMA16816 (acc[mi][nj], fa[mi], fb[jg][jl], fb[jg][2 + jl]);
                    }
            }
        }
        CP_WAIT0();
        __syncthreads();

        float* Csm = (float*)sm;
        #pragma unroll
        for (int mi = 0; mi < 4; mi++)
            #pragma unroll
            for (int nj = 0; nj < 4; nj++){
                const int r  = wm*64 + mi*16 + (lane >> 2);
                const int cc = wn*32 + nj*8  + (lane & 3)*2;
                *(float2*)&Csm[r*132 + cc]       = make_float2(acc[mi][nj][0], acc[mi][nj][1]);
                *(float2*)&Csm[(r + 8)*132 + cc] = make_float2(acc[mi][nj][2], acc[mi][nj][3]);
            }
        __syncthreads();

        #pragma unroll 1
        for (int it = 0; it < 16; it++){
            const int i = it*256 + tid;
            const int row = i >> 5;
            const int cq  = (i & 31) << 2;
            const float* cp = Csm + row*132 + cq;
            float a0 = cp[0], a1 = cp[1], a2 = cp[2], a3 = cp[3];
            const size_t gb = (size_t)(bm + row)*N + bn + cq;
            if (EPI == 1){
                const float4 r4 = *(const float4*)(res + gb);
                float4 o = {a0 + r4.x, a1 + r4.y, a2 + r4.z, a3 + r4.w};
                *(float4*)(C + gb) = o;
            } else if (EPI == 2){
                const float4 b4 = *(const float4*)(bias + bn + cq);
                float v0 = fmaxf(a0 + b4.x, 0.f), v1 = fmaxf(a1 + b4.y, 0.f);
                float v2 = fmaxf(a2 + b4.z, 0.f), v3 = fmaxf(a3 + b4.w, 0.f);
                *(__half2*)((__half*)Oh + gb)     = __floats2half2_rn(v0, v1);
                *(__half2*)((__half*)Oh + gb + 2) = __floats2half2_rn(v2, v3);
            } else if (EPI == 3){
                const float4 b4 = *(const float4*)(bias + bn + cq);
                const float4 r4 = *(const float4*)(res + gb);
                float4 o = {a0 + b4.x + r4.x, a1 + b4.y + r4.y,
                            a2 + b4.z + r4.z, a3 + b4.w + r4.w};
                *(float4*)(C + gb) = o;
            } else {
                const int col = bn + cq;
                const int sel = col >> 10;
                const int h   = (col & 1023) >> 6;
                const int d   = col & 63;
                const int tv  = bm + row;
                const size_t bhs = ((size_t)(((tv >> 11)*HH) + h)*SS + (tv & 2047));
                const float QSC = 0.125f * 1.44269504088896340736f;
                if (sel == 0){
                    __nv_bfloat162 o0; o0.x = __float2bfloat16(a0*QSC); o0.y = __float2bfloat16(a1*QSC);
                    __nv_bfloat162 o1; o1.x = __float2bfloat16(a2*QSC); o1.y = __float2bfloat16(a3*QSC);
                    *(__nv_bfloat162*)(Oh + bhs*96 + d)     = o0;
                    *(__nv_bfloat162*)(Oh + bhs*96 + d + 2) = o1;
                } else if (sel == 1){
                    __nv_bfloat162 o0; o0.x = __float2bfloat16(a0); o0.y = __float2bfloat16(a1);
                    __nv_bfloat162 o1; o1.x = __float2bfloat16(a2); o1.y = __float2bfloat16(a3);
                    *(__nv_bfloat162*)(Ol + bhs*96 + d)     = o0;
                    *(__nv_bfloat162*)(Ol + bhs*96 + d + 2) = o1;
                } else {
                    __nv_bfloat162 o0; o0.x = __float2bfloat16(a0); o0.y = __float2bfloat16(a1);
                    __nv_bfloat162 o1; o1.x = __float2bfloat16(a2); o1.y = __float2bfloat16(a3);
                    *(__nv_bfloat162*)(Vo + bhs*64 + d)     = o0;
                    *(__nv_bfloat162*)(Vo + bhs*64 + d + 2) = o1;
                }
            }
        }
    }
}

// ============ unified weight prep ============
__global__ __launch_bounds__(256) void wprep(
    const float* __restrict__ Wq, const float* __restrict__ Wk,
    const float* __restrict__ Wv, const float* __restrict__ Wo,
    const float* __restrict__ W1, const float* __restrict__ W2)
{
    __shared__ float t[32][33];
    const int id = blockIdx.x;
    const float* W; __nv_bfloat16* T; int K, N, bx, by, f16;
    if (id < 4096){
        const int s = id >> 10, r = id & 1023;
        if (s < 3){ W = s == 0 ? Wq : (s == 1 ? Wk : Wv); T = g_wqkvh + (size_t)s*DD*DD; }
        else      { W = Wo; T = g_woh; }
        K = DD; N = DD; bx = r & 31; by = r >> 5; f16 = 0;
    } else if (id < 8192){
        const int r = id - 4096; W = W1; T = g_w1; K = DD; N = MLPD;
        bx = r & 127; by = r >> 7; f16 = 1;
    } else {
        const int r = id - 8192; W = W2; T = g_w2; K = MLPD; N = DD;
        bx = r & 31; by = r >> 5; f16 = 1;
    }
    const int tx = threadIdx.x & 31, ty = threadIdx.x >> 5;
    const int k0 = by*32, n0 = bx*32;
    #pragma unroll
    for (int i = 0; i < 4; i++)
        t[ty + i*8][tx] = W[(size_t)(k0 + ty + i*8)*N + n0 + tx];
    __syncthreads();
    #pragma unroll
    for (int i = 0; i < 4; i++){
        const int n = n0 + ty + i*8;
        const float x = t[tx][ty + i*8];
        if (f16) ((__half*)T)[(size_t)n*K + k0 + tx] = __float2half(x);
        else     T[(size_t)n*K + k0 + tx] = __float2bfloat16(x);
    }
}

__global__ __launch_bounds__(256) void wtrans(
    const float* __restrict__ Whq, const float* __restrict__ Whk,
    __nv_bfloat16* __restrict__ WT)
{
    const int h = blockIdx.x, m = blockIdx.y;
    const float* src = m ? Whk : Whq;
    const float sc = m ? 1.f : (1.f/(0.125f*1.44269504088896340736f));
    for (int i = threadIdx.x; i < DHH*NBB; i += 256){
        const int f = i >> 5, n = i & 31;
        WT[(((size_t)m*HH + h)*NBB + n)*64 + f] =
            __float2bfloat16(src[((size_t)h*DHH + f)*NBB + n]*sc);
    }
}

// ============ LayerNorm: MODE 0 = bf16 out, 1 = fp16 out ============
template<int MODE>
__global__ __launch_bounds__(256) void ln_split(
    const float* __restrict__ in, const float* __restrict__ g,
    const float* __restrict__ bta, __nv_bfloat16* __restrict__ oh)
{
    __shared__ float red[256];
    const int t = blockIdx.x, tid = threadIdx.x;
    const float4 x = ((const float4*)(in + (size_t)t*DD))[tid];

    float sum = x.x + x.y + x.z + x.w;
    red[tid] = sum; __syncthreads();
    #pragma unroll
    for (int o = 128; o > 0; o >>= 1) { if (tid < o) red[tid] += red[tid+o]; __syncthreads(); }
    const float mu = red[0] * (1.0f/DD);
    __syncthreads();

    float d0 = x.x-mu, d1 = x.y-mu, d2 = x.z-mu, d3 = x.w-mu;
    red[tid] = d0*d0 + d1*d1 + d2*d2 + d3*d3; __syncthreads();
    #pragma unroll
    for (int o = 128; o > 0; o >>= 1) { if (tid < o) red[tid] += red[tid+o]; __syncthreads(); }
    const float rs = rsqrtf(red[0]*(1.0f/DD) + 1e-6f);

    const float4 gg = ((const float4*)g)[tid];
    const float4 bb = ((const float4*)bta)[tid];
    float y0 = d0*rs*gg.x + bb.x, y1 = d1*rs*gg.y + bb.y;
    float y2 = d2*rs*gg.z + bb.z, y3 = d3*rs*gg.w + bb.w;

    if (MODE == 0){
        __nv_bfloat162 hp0; hp0.x = __float2bfloat16(y0); hp0.y = __float2bfloat16(y1);
        __nv_bfloat162 hp1; hp1.x = __float2bfloat16(y2); hp1.y = __float2bfloat16(y3);
        __nv_bfloat162* ph = (__nv_bfloat162*)(oh + (size_t)t*DD);
        ph[tid*2] = hp0; ph[tid*2 + 1] = hp1;
    } else {
        __half2* ph = (__half2*)((__half*)oh + (size_t)t*DD);
        ph[tid*2]     = __floats2half2_rn(y0, y1);
        ph[tid*2 + 1] = __floats2half2_rn(y2, y3);
    }
}

// ============ bucket softmax via mma (static shift) + fused partial sums ============
#define B2SM 41472
__global__ __launch_bounds__(128) void bucket2(
    const __nv_bfloat16* __restrict__ Qa, const __nv_bfloat16* __restrict__ Ka,
    const __nv_bfloat16* __restrict__ WT, float* __restrict__ bpart,
    __nv_bfloat16* __restrict__ Qao, __nv_bfloat16* __restrict__ Kao)
{
    extern __shared__ char sm[];
    const uint32_t smu = smem_u32(sm);
    const int tid = threadIdx.x, wid = tid >> 5, lane = tid & 31;
    const int h = blockIdx.x;
    const int ty = blockIdx.y, bq = ty >> 4, sbase = (ty & 15)*128;
    const int bh = bq*HH + h;
    const uint32_t Qs = smu, Ks = smu + 16384u, Ws = smu + 32768u;
    float* csum = (float*)(sm + 40960);

    const size_t qa0 = ((size_t)bh*SS + sbase)*96;
    for (int i = tid; i < 128*8; i += 128){
        const int r = i >> 3, c = i & 7;
        const uint32_t off = (uint32_t)(r*128) + (uint32_t)((c ^ (r & 7)) << 4);
        CPA16(Qs + off, (const char*)(Qa + qa0 + (size_t)r*96 + c*8));
        CPA16(Ks + off, (const char*)(Ka + qa0 + (size_t)r*96 + c*8));
    }
    for (int i = tid; i < 2*32*8; i += 128){
        const int m = i >> 8, r = (i >> 3) & 31, c = i & 7;
        CPA16(Ws + (uint32_t)(m*4096) + (uint32_t)(r*128) + (uint32_t)((c ^ (r & 7)) << 4),
              (const char*)(WT + ((size_t)m*HH + h)*NBB*64 + (size_t)r*64 + c*8));
    }
    CP_COMMIT(); CP_WAIT0(); __syncthreads();

    const int grp = lane >> 3, rin = lane & 7;
    const int roff = (grp & 1)*8 + rin, chi = grp >> 1;
    const float BSC = 0.1f * 1.44269504088896340736f;

    #pragma unroll
    for (int m = 0; m < 2; m++){
        const uint32_t As = m ? Ks : Qs;
        const uint32_t Bs = Ws + (uint32_t)m*4096u;
        float acc[2][4][4];
        #pragma unroll
        for (int mi = 0; mi < 2; mi++)
            #pragma unroll
            for (int nj = 0; nj < 4; nj++)
                #pragma unroll
                for (int e = 0; e < 4; e++) acc[mi][nj][e] = 0.f;

        #pragma unroll
        for (int ks = 0; ks < 4; ks++){
            uint32_t fa[2][4], fb0[4], fb1[4];
            #pragma unroll
            for (int mi = 0; mi < 2; mi++){
                const int r = wid*32 + mi*16 + roff;
                LDSM4(fa[mi], As + (uint32_t)(r*128) + (uint32_t)(((2*ks + chi) ^ (r & 7)) << 4));
            }
            { const int r = roff;      LDSM4(fb0, Bs + (uint32_t)(r*128) + (uint32_t)(((2*ks + chi) ^ (r & 7)) << 4)); }
            { const int r = 16 + roff; LDSM4(fb1, Bs + (uint32_t)(r*128) + (uint32_t)(((2*ks + chi) ^ (r & 7)) << 4)); }
            #pragma unroll
            for (int mi = 0; mi < 2; mi++){
                MMA16816(acc[mi][0], fa[mi], fb0[0], fb0[2]);
                MMA16816(acc[mi][1], fa[mi], fb0[1], fb0[3]);
                MMA16816(acc[mi][2], fa[mi], fb1[0], fb1[2]);
                MMA16816(acc[mi][3], fa[mi], fb1[1], fb1[3]);
            }
        }

        float local8[8];
        #pragma unroll
        for (int e = 0; e < 8; e++) local8[e] = 0.f;

        #pragma unroll
        for (int mi = 0; mi < 2; mi++){
            float s0v = 0.f, s1v = 0.f;
            #pragma unroll
            for (int nj = 0; nj < 4; nj++){
                acc[mi][nj][0] = __expf(acc[mi][nj][0]); s0v += acc[mi][nj][0];
                acc[mi][nj][1] = __expf(acc[mi][nj][1]); s0v += acc[mi][nj][1];
                acc[mi][nj][2] = __expf(acc[mi][nj][2]); s1v += acc[mi][nj][2];
                acc[mi][nj][3] = __expf(acc[mi][nj][3]); s1v += acc[mi][nj][3];
            }
            s0v += __shfl_xor_sync(~0u, s0v, 1); s0v += __shfl_xor_sync(~0u, s0v, 2);
            s1v += __shfl_xor_sync(~0u, s1v, 1); s1v += __shfl_xor_sync(~0u, s1v, 2);
            const float i0 = 1.f/s0v, i1 = 1.f/s1v;
            const int r_lo = wid*32 + mi*16 + (lane >> 2);
            const int srow0 = sbase + r_lo, srow1 = srow0 + 8;
            __nv_bfloat16* oo = m ? Kao : Qao;
            const float sc = m ? 1.f : BSC;
            #pragma unroll
            for (int nj = 0; nj < 4; nj++){
                const int cc = nj*8 + (lane & 3)*2;
                float p0 = acc[mi][nj][0]*i0, p1 = acc[mi][nj][1]*i0;
                float p2 = acc[mi][nj][2]*i1, p3 = acc[mi][nj][3]*i1;
                local8[nj*2]     += p0 + p2;
                local8[nj*2 + 1] += p1 + p3;
                __nv_bfloat162 o0; o0.x = __float2bfloat16(p0*sc); o0.y = __float2bfloat16(p1*sc);
                __nv_bfloat162 o1; o1.x = __float2bfloat16(p2*sc); o1.y = __float2bfloat16(p3*sc);
                *(__nv_bfloat162*)(oo + ((size_t)bh*SS + srow0)*96 + 64 + cc) = o0;
                *(__nv_bfloat162*)(oo + ((size_t)bh*SS + srow1)*96 + 64 + cc) = o1;
            }
        }

        #pragma unroll
        for (int e = 0; e < 8; e++){
            local8[e] += __shfl_down_sync(~0u, local8[e], 16);
            local8[e] += __shfl_down_sync(~0u, local8[e], 8);
            local8[e] += __shfl_down_sync(~0u, local8[e], 4);
        }
        if ((lane >> 2) == 0){
            #pragma unroll
            for (int nj = 0; nj < 4; nj++){
                csum[wid*32 + nj*8 + lane*2]     = local8[nj*2];
                csum[wid*32 + nj*8 + lane*2 + 1] = local8[nj*2 + 1];
            }
        }
        __syncthreads();
        if (tid < 32){
            const float v = csum[tid] + csum[32 + tid] + csum[64 + tid] + csum[96 + tid];
            bpart[(((size_t)m*HH + h)*NT + ty)*NBB + tid] = v;
        }
        __syncthreads();
    }
}

// ============ flash attention: static-shift softmax ============
#define FSM 65536
#define CSH 24.0f
__global__ __launch_bounds__(256, 2) void flash_mma(
    const __nv_bfloat16* __restrict__ Qa, const __nv_bfloat16* __restrict__ Ka,
    const __nv_bfloat16* __restrict__ Vb, __nv_bfloat16* __restrict__ ah)
{
    extern __shared__ char sm[];
    const uint32_t smu = smem_u32(sm);
    const int tid = threadIdx.x, wid = tid >> 5, lane = tid & 31;
    const int bh = blockIdx.x, b = bh >> 4, h = bh & 15;
    const int q0 = blockIdx.y * 128;

    const uint32_t QC = smu, QB = smu + 16384u;
    const uint32_t ST0 = smu + 24576u;

    {
        const size_t qb0 = ((size_t)bh*SS + q0)*96;
        #pragma unroll
        for (int i = 0; i < 4; i++){
            const int q = tid + i*256, r = q >> 3, c = q & 7;
            CPA16(QC + (uint32_t)(r*128) + (uint32_t)(((c ^ (r & 7)) << 4)),
                  (const char*)(Qa + qb0 + (size_t)r*96 + c*8));
        }
        #pragma unroll
        for (int i = 0; i < 2; i++){
            const int q = tid + i*256, r = q >> 2, c = q & 3;
            CPA16(QB + (uint32_t)(r*64) + (uint32_t)(((c ^ ((r >> 1) & 3)) << 4)),
                  (const char*)(Qa + qb0 + (size_t)r*96 + 64 + c*8));
        }
        CP_COMMIT();
    }
    auto issueKV = [&](int it, uint32_t st){
        const size_t kb0 = ((size_t)bh*SS + it*64)*96;
        const size_t vb0 = ((size_t)bh*SS + it*64)*64;
        #pragma unroll
        for (int i = 0; i < 2; i++){
            const int q = tid + i*256, r = q >> 3, c = q & 7;
            CPA16(st + (uint32_t)(r*128) + (uint32_t)((c ^ (r & 7)) << 4),
                  (const char*)(Ka + kb0 + (size_t)r*96 + c*8));
        }
        {
            const int r = tid >> 2, c = tid & 3;
            CPA16(st + 8192u + (uint32_t)(r*64) + (uint32_t)((c ^ ((r >> 1) & 3)) << 4),
                  (const char*)(Ka + kb0 + (size_t)r*96 + 64 + c*8));
        }
        #pragma unroll
        for (int i = 0; i < 2; i++){
            const int q = tid + i*256, r = q >> 3, c = q & 7;
            CPA16(st + 12288u + (uint32_t)(r*128) + (uint32_t)((c ^ (r & 7)) << 4),
                  (const char*)(Vb + vb0 + (size_t)r*64 + c*8));
        }
        CP_COMMIT();
    };
    issueKV(0, ST0);
    issueKV(1, ST0 + 20480u);

    CP_WAIT2();
    __syncthreads();

    const int grp = lane >> 3, rin = lane & 7;
    const int roff = (grp & 1)*8 + rin, chi = grp >> 1;

    uint32_t qf[6][4];
    {
        const int r = wid*16 + roff;
        #pragma unroll
        for (int ks = 0; ks < 4; ks++)
            LDSM4(qf[ks], QC + (uint32_t)(r*128) + (uint32_t)(((2*ks + chi) ^ (r & 7)) << 4));
        #pragma unroll
        for (int ks = 0; ks < 2; ks++)
            LDSM4(qf[4 + ks], QB + (uint32_t)(r*64) + (uint32_t)(((2*ks + chi) ^ ((r >> 1) & 3)) << 4));
    }

    float oacc[8][4];
    #pragma unroll
    for (int nt = 0; nt < 8; nt++)
        #pragma unroll
        for (int e = 0; e < 4; e++) oacc[nt][e] = 0.f;
    float l0 = 0.f, l1 = 0.f;

    for (int it = 0; it < SS/64; it++){
        const uint32_t st = ST0 + (uint32_t)(it & 1)*20480u;
        if (it + 1 < SS/64) CP_WAIT1(); else CP_WAIT0();
        __syncthreads();

        float sacc[8][4];
        #pragma unroll
        for (int nt = 0; nt < 8; nt++)
            #pragma unroll
            for (int e = 0; e < 4; e++) sacc[nt][e] = 0.f;

        #pragma unroll
        for (int ks = 0; ks < 6; ks++){
            #pragma unroll
            for (int p = 0; p < 4; p++){
                uint32_t bf[4];
                const int r = p*16 + roff;
                if (ks < 4)
                    LDSM4(bf, st + (uint32_t)(r*128) + (uint32_t)(((2*ks + chi) ^ (r & 7)) << 4));
                else
                    LDSM4(bf, st + 8192u + (uint32_t)(r*64) + (uint32_t)(((2*(ks-4) + chi) ^ ((r >> 1) & 3)) << 4));
                MMA16816(sacc[2*p],     qf[ks], bf[0], bf[2]);
                MMA16816(sacc[2*p + 1], qf[ks], bf[1], bf[3]);
            }
        }

        #pragma unroll
        for (int nt = 0; nt < 8; nt++){
            sacc[nt][0] = exp2f(sacc[nt][0] - CSH); l0 += sacc[nt][0];
            sacc[nt][1] = exp2f(sacc[nt][1] - CSH); l0 += sacc[nt][1];
            sacc[nt][2] = exp2f(sacc[nt][2] - CSH); l1 += sacc[nt][2];
            sacc[nt][3] = exp2f(sacc[nt][3] - CSH); l1 += sacc[nt][3];
        }

        uint32_t pf[4][4];
        #pragma unroll
        for (int kk = 0; kk < 4; kk++){
            PACKBF(pf[kk][0], sacc[2*kk][0],     sacc[2*kk][1]);
            PACKBF(pf[kk][1], sacc[2*kk][2],     sacc[2*kk][3]);
            PACKBF(pf[kk][2], sacc[2*kk + 1][0], sacc[2*kk + 1][1]);
            PACKBF(pf[kk][3], sacc[2*kk + 1][2], sacc[2*kk + 1][3]);
        }

        #pragma unroll
        for (int kk = 0; kk < 4; kk++){
            #pragma unroll
            for (int p = 0; p < 4; p++){
                uint32_t bv[4];
                const int vrow = kk*16 + (grp >> 1)*8 + rin;
                LDSM4T(bv, st + 12288u + (uint32_t)(vrow*128)
                           + (uint32_t)(((2*p + (grp & 1)) ^ (vrow & 7)) << 4));
                MMA16816(oacc[2*p],     pf[kk], bv[0], bv[2]);
                MMA16816(oacc[2*p + 1], pf[kk], bv[1], bv[3]);
            }
        }
        __syncthreads();
        if (it + 2 < SS/64) issueKV(it + 2, st);
    }

    l0 += __shfl_xor_sync(0xffffffffu, l0, 1);
    l0 += __shfl_xor_sync(0xffffffffu, l0, 2);
    l1 += __shfl_xor_sync(0xffffffffu, l1, 1);
    l1 += __shfl_xor_sync(0xffffffffu, l1, 2);
    const float inv0 = 1.f / l0, inv1 = 1.f / l1;
    const int r0g = q0 + wid*16 + (lane >> 2);
    const size_t t0 = (size_t)(b*SS + r0g), t1 = t0 + 8;
    const int cb = h*DHH + 2*(lane & 3);
    #pragma unroll
    for (int j = 0; j < 8; j++){
        const float v0 = oacc[j][0]*inv0, v1 = oacc[j][1]*inv0;
        const float v2 = oacc[j][2]*inv1, v3 = oacc[j][3]*inv1;
        __nv_bfloat162 hp0; hp0.x = __float2bfloat16(v0); hp0.y = __float2bfloat16(v1);
        __nv_bfloat162 hp1; hp1.x = __float2bfloat16(v2); hp1.y = __float2bfloat16(v3);
        *(__nv_bfloat162*)(ah + t0*DD + cb + 8*j) = hp0;
        *(__nv_bfloat162*)(ah + t1*DD + cb + 8*j) = hp1;
    }
}

// ============ aux loss ============
__global__ __launch_bounds__(512) void msum_loss(
    const float* __restrict__ bpart, float* __restrict__ out, int out_idx)
{
    __shared__ float red[512];
    const int tid = threadIdx.x;
    const int h = tid >> 5, n = tid & 31;
    float sq = 0.f, sk = 0.f;
    #pragma unroll 8
    for (int t = 0; t < NT; t++){
        sq += bpart[(((size_t)0*HH + h)*NT + t)*NBB + n];
        sk += bpart[(((size_t)1*HH + h)*NT + t)*NBB + n];
    }
    const float mq = sq * (1.0f/TOK), mk = sk * (1.0f/TOK);
    red[tid] = mq*mq + mk*mk; __syncthreads();
    #pragma unroll
    for (int o = 256; o > 0; o >>= 1) { if (tid < o) red[tid] += red[tid+o]; __syncthreads(); }
    if (tid == 0) out[out_idx] = 0.5f * (float)NBB * red[0] / (float)HH;
}

// ============ host launch ============
extern "C" void kernel_launch(void* const* d_in, const int* in_sizes, int n_in,
                              void* d_out, int out_size)
{
    const float* inputs = (const float*)d_in[0];
    const float* ln1_g  = (const float*)d_in[1];
    const float* ln1_b  = (const float*)d_in[2];
    const float* Wq     = (const float*)d_in[3];
    const float* Wk     = (const float*)d_in[4];
    const float* Wv     = (const float*)d_in[5];
    const float* Whq    = (const float*)d_in[6];
    const float* Whk    = (const float*)d_in[7];
    const float* Wo     = (const float*)d_in[8];
    const float* ln2_g  = (const float*)d_in[9];
    const float* ln2_b  = (const float*)d_in[10];
    const float* W1     = (const float*)d_in[11];
    const float* b1     = (const float*)d_in[12];
    const float* W2     = (const float*)d_in[13];
    const float* b2     = (const float*)d_in[14];
    float* out = (float*)d_out;

    __nv_bfloat16 *p_xh, *p_ah, *p_y, *p_h1;
    __nv_bfloat16 *p_wqkvh, *p_woh, *p_w1, *p_w2;
    __nv_bfloat16 *p_Qa, *p_Ka, *p_Vb, *p_wt;
    float *p_x, *p_bpart;
    cudaGetSymbolAddress((void**)&p_xh, g_xh);
    cudaGetSymbolAddress((void**)&p_ah, g_ah);
    cudaGetSymbolAddress((void**)&p_x, g_x);
    cudaGetSymbolAddress((void**)&p_y, g_y);
    cudaGetSymbolAddress((void**)&p_h1, g_h1);
    cudaGetSymbolAddress((void**)&p_bpart, g_bpart);
    cudaGetSymbolAddress((void**)&p_wqkvh, g_wqkvh);
    cudaGetSymbolAddress((void**)&p_woh, g_woh);
    cudaGetSymbolAddress((void**)&p_w1, g_w1);
    cudaGetSymbolAddress((void**)&p_w2, g_w2);
    cudaGetSymbolAddress((void**)&p_Qa, g_Qa);   cudaGetSymbolAddress((void**)&p_Ka, g_Ka);
    cudaGetSymbolAddress((void**)&p_Vb, g_Vb);   cudaGetSymbolAddress((void**)&p_wt, g_wt);

    cudaFuncSetAttribute((const void*)mma_gemm<4,0>, cudaFuncAttributeMaxDynamicSharedMemorySize, GSM);
    cudaFuncSetAttribute((const void*)mma_gemm<1,0>, cudaFuncAttributeMaxDynamicSharedMemorySize, GSM);
    cudaFuncSetAttribute((const void*)mma_gemm<2,1>, cudaFuncAttributeMaxDynamicSharedMemorySize, GSM);
    cudaFuncSetAttribute((const void*)mma_gemm<3,1>, cudaFuncAttributeMaxDynamicSharedMemorySize, GSM);
    cudaFuncSetAttribute((const void*)flash_mma, cudaFuncAttributeMaxDynamicSharedMemorySize, FSM);
    cudaFuncSetAttribute((const void*)bucket2, cudaFuncAttributeMaxDynamicSharedMemorySize, B2SM);

    ln_split<0><<<TOK, 256>>>(inputs, ln1_g, ln1_b, p_xh);                         // 1
    wprep<<<12288, 256>>>(Wq, Wk, Wv, Wo, W1, W2);                                 // 2
    wtrans<<<dim3(HH,2), 256>>>(Whq, Whk, p_wt);                                   // 3
    mma_gemm<4,0><<<PGRID, 256, GSM>>>(                                            // 4: QKV (profiled)
        p_xh, p_wqkvh, nullptr, nullptr, nullptr, p_Qa, p_Ka, p_Vb,
        TOK, QKVD, DD);
    bucket2<<<dim3(HH, NT), 128, B2SM>>>(p_Qa, p_Ka, p_wt, p_bpart, p_Qa, p_Ka);   // 5
    flash_mma<<<dim3(BH, SS/128), 256, FSM>>>(p_Qa, p_Ka, p_Vb, p_ah);             // 6
    mma_gemm<1,0><<<256, 256, GSM>>>(                                              // 7: Wo + residual
        p_ah, p_woh, p_x, nullptr, inputs, nullptr, nullptr, nullptr,
        TOK, DD, DD);
    ln_split<1><<<TOK, 256>>>(p_x, ln2_g, ln2_b, p_y);                             // 8
    mma_gemm<2,1><<<PGRID, 256, GSM>>>(                                            // 9: MLP1 fp16
        p_y, p_w1, nullptr, b1, nullptr, p_h1, nullptr, nullptr,
        TOK, MLPD, DD);
    mma_gemm<3,1><<<256, 256, GSM>>>(                                              // 10: MLP2 fp16
        p_h1, p_w2, out, b2, p_x, nullptr, nullptr, nullptr,
        TOK, DD, MLPD);
    msum_loss<<<1, 512>>>(p_bpart, out, out_size - 1);                             // 11
}

// round 17
// speedup vs baseline: 1.2282x; 1.0254x over previous
#include <cuda_runtime.h>
#include <cuda_bf16.h>
#include <cuda_fp16.h>
#include <math.h>
#include <stdint.h>

#define BB   2
#define SS   2048
#define DD   1024
#define HH   16
#define DHH  64
#define NBB  32
#define MLPD 4096
#define TOK  (BB*SS)
#define HN   (HH*NBB)
#define QKVD 3072
#define BH   (BB*HH)
#define NT   (TOK/128)

__device__ __align__(128) __nv_bfloat16 g_xh [TOK*DD];
__device__ __align__(128) __nv_bfloat16 g_ah [TOK*DD];
__device__ __align__(128) float         g_x  [TOK*DD];
__device__ __align__(128) __nv_bfloat16 g_y  [TOK*DD];        // fp16 payload
__device__ __align__(128) __nv_bfloat16 g_h1 [TOK*MLPD];      // fp16 payload
__device__ __align__(128) float         g_bpart[2*HH*NT*NBB];
__device__ __align__(128) __nv_bfloat16 g_wqkvh[QKVD*DD];
__device__ __align__(128) __nv_bfloat16 g_woh [DD*DD];
__device__ __align__(128) __nv_bfloat16 g_w1 [MLPD*DD];       // fp16 payload
__device__ __align__(128) __nv_bfloat16 g_w2 [DD*MLPD];       // fp16 payload
__device__ __align__(128) __nv_bfloat16 g_Qa [BH*SS*96];
__device__ __align__(128) __nv_bfloat16 g_Ka [BH*SS*96];
__device__ __align__(128) __nv_bfloat16 g_Vb [BH*SS*64];
__device__ __align__(128) __nv_bfloat16 g_wt [2*HH*NBB*64];

__device__ __forceinline__ uint32_t smem_u32(const void* p){
    uint32_t a;
    asm("{ .reg .u64 t; cvta.to.shared.u64 t, %1; cvt.u32.u64 %0, t; }" : "=r"(a) : "l"(p));
    return a;
}
#define CPA16(dst, src) \
    asm volatile("cp.async.cg.shared.global [%0], [%1], 16;" :: "r"(dst), "l"(src))
#define CP_COMMIT() asm volatile("cp.async.commit_group;" ::: "memory")
#define CP_WAIT2()  asm volatile("cp.async.wait_group 2;" ::: "memory")
#define CP_WAIT1()  asm volatile("cp.async.wait_group 1;" ::: "memory")
#define CP_WAIT0()  asm volatile("cp.async.wait_group 0;" ::: "memory")
#define LDSM4(r, addr) \
    asm volatile("ldmatrix.sync.aligned.m8n8.x4.shared.b16 {%0,%1,%2,%3}, [%4];" \
        : "=r"((r)[0]), "=r"((r)[1]), "=r"((r)[2]), "=r"((r)[3]) : "r"(addr))
#define LDSM4T(r, addr) \
    asm volatile("ldmatrix.sync.aligned.m8n8.x4.trans.shared.b16 {%0,%1,%2,%3}, [%4];" \
        : "=r"((r)[0]), "=r"((r)[1]), "=r"((r)[2]), "=r"((r)[3]) : "r"(addr))
#define MMA16816(d, a, b0, b1) \
    asm volatile("mma.sync.aligned.m16n8k16.row.col.f32.bf16.bf16.f32 " \
        "{%0,%1,%2,%3}, {%4,%5,%6,%7}, {%8,%9}, {%0,%1,%2,%3};" \
        : "+f"((d)[0]), "+f"((d)[1]), "+f"((d)[2]), "+f"((d)[3]) \
        : "r"((a)[0]), "r"((a)[1]), "r"((a)[2]), "r"((a)[3]), "r"(b0), "r"(b1))
#define MMAH16816(d, a, b0, b1) \
    asm volatile("mma.sync.aligned.m16n8k16.row.col.f32.f16.f16.f32 " \
        "{%0,%1,%2,%3}, {%4,%5,%6,%7}, {%8,%9}, {%0,%1,%2,%3};" \
        : "+f"((d)[0]), "+f"((d)[1]), "+f"((d)[2]), "+f"((d)[3]) \
        : "r"((a)[0]), "r"((a)[1]), "r"((a)[2]), "r"((a)[3]), "r"(b0), "r"(b1))
#define PACKBF(d, lo, hi) \
    asm("cvt.rn.bf16x2.f32 %0, %1, %2;" : "=r"(d) : "f"(hi), "f"(lo))

// ===== mma.sync GEMM: CTA 128x128, warp 64x32, K-chunk 32, 4-stage, occ 2 (R13 champion) =====
// EPI: 1 +res fp32 | 2 +bias,relu->fp16 | 3 +bias+res fp32 | 4 qkv->Qa/Ka/Vb
#define SBQ  16384u
#define GSM  (128*132*4)

template<int EPI, int F16>
__global__ __launch_bounds__(256, 2) void mma_gemm(
    const __nv_bfloat16* __restrict__ A, const __nv_bfloat16* __restrict__ B,
    float* __restrict__ C, const float* __restrict__ bias, const float* __restrict__ res,
    __nv_bfloat16* __restrict__ Oh, __nv_bfloat16* __restrict__ Ol,
    __nv_bfloat16* __restrict__ Vo,
    int M, int N, int K)
{
    extern __shared__ char sm[];
    const uint32_t smu = smem_u32(sm);
    const int tid = threadIdx.x;
    const int wid = tid >> 5, lane = tid & 31;
    const int bm = blockIdx.y * 128, bn = blockIdx.x * 128;
    const int wm = wid >> 2, wn = wid & 3;

    const int prow = tid >> 1, phalf = tid & 1;
    const uint32_t psw = (uint32_t)((prow >> 1) & 3);
    const uint32_t pd0 = (uint32_t)(prow*64) + ((((uint32_t)phalf*2u + 0u) ^ psw) << 4);
    const uint32_t pd1 = (uint32_t)(prow*64) + ((((uint32_t)phalf*2u + 1u) ^ psw) << 4);
    const __nv_bfloat16* gA = A + (size_t)(bm + prow)*K + phalf*16;
    const __nv_bfloat16* gB = B + (size_t)(bn + prow)*K + phalf*16;

    const int g   = lane >> 3, rin = lane & 7;
    const int roff = (g & 1)*8 + rin;
    const uint32_t chi = (uint32_t)(g >> 1);
    uint32_t aRow[4], aSw[4], bRow[2], bSw[2];
    #pragma unroll
    for (int mi = 0; mi < 4; mi++){
        const int r = wm*64 + mi*16 + roff;
        aRow[mi] = (uint32_t)(r*64); aSw[mi] = (uint32_t)((r >> 1) & 3);
    }
    #pragma unroll
    for (int nj = 0; nj < 2; nj++){
        const int r = wn*32 + nj*16 + roff;
        bRow[nj] = (uint32_t)(r*64); bSw[nj] = (uint32_t)((r >> 1) & 3);
    }

    float acc[4][4][4];
    #pragma unroll
    for (int mi = 0; mi < 4; mi++)
        #pragma unroll
        for (int nj = 0; nj < 4; nj++)
            #pragma unroll
            for (int e = 0; e < 4; e++) acc[mi][nj][e] = 0.f;

    auto issue = [&](int c, uint32_t st){
        const int kc = c << 5;
        CPA16(st + pd0, gA + kc); CPA16(st + pd1, gA + kc + 8);
        CPA16(st + 8192u + pd0, gB + kc); CPA16(st + 8192u + pd1, gB + kc + 8);
        CP_COMMIT();
    };

    const int nch = K >> 5;
    issue(0, smu);
    issue(1, smu + SBQ);
    issue(2, smu + 2u*SBQ);

    for (int c = 0; c < nch; c++){
        const uint32_t st = smu + (uint32_t)(c & 3)*SBQ;
        CP_WAIT2();
        __syncthreads();
        if (c + 3 < nch) issue(c + 3, smu + (uint32_t)((c + 3) & 3)*SBQ);
        else CP_COMMIT();

        #pragma unroll
        for (int ks = 0; ks < 2; ks++){
            const uint32_t ch = (uint32_t)(ks*2) + chi;
            uint32_t fa[4][4], fb[2][4];
            #pragma unroll
            for (int mi = 0; mi < 4; mi++)
                LDSM4(fa[mi], st + aRow[mi] + ((ch ^ aSw[mi]) << 4));
            #pragma unroll
            for (int nj = 0; nj < 2; nj++)
                LDSM4(fb[nj], st + 8192u + bRow[nj] + ((ch ^ bSw[nj]) << 4));
            #pragma unroll
            for (int mi = 0; mi < 4; mi++)
                #pragma unroll
                for (int nj = 0; nj < 4; nj++){
                    const int jg = nj >> 1, jl = nj & 1;
                    if (F16) MMAH16816(acc[mi][nj], fa[mi], fb[jg][jl], fb[jg][2 + jl]);
                    else     MMA16816 (acc[mi][nj], fa[mi], fb[jg][jl], fb[jg][2 + jl]);
                }
        }
    }
    CP_WAIT0();
    __syncthreads();

    float* Csm = (float*)sm;
    #pragma unroll
    for (int mi = 0; mi < 4; mi++)
        #pragma unroll
        for (int nj = 0; nj < 4; nj++){
            const int r  = wm*64 + mi*16 + (lane >> 2);
            const int cc = wn*32 + nj*8  + (lane & 3)*2;
            *(float2*)&Csm[r*132 + cc]       = make_float2(acc[mi][nj][0], acc[mi][nj][1]);
            *(float2*)&Csm[(r + 8)*132 + cc] = make_float2(acc[mi][nj][2], acc[mi][nj][3]);
        }
    __syncthreads();

    #pragma unroll 1
    for (int it = 0; it < 16; it++){
        const int i = it*256 + tid;
        const int row = i >> 5;
        const int cq  = (i & 31) << 2;
        const float* cp = Csm + row*132 + cq;
        float a0 = cp[0], a1 = cp[1], a2 = cp[2], a3 = cp[3];
        const size_t gb = (size_t)(bm + row)*N + bn + cq;
        if (EPI == 1){
            const float4 r4 = *(const float4*)(res + gb);
            float4 o = {a0 + r4.x, a1 + r4.y, a2 + r4.z, a3 + r4.w};
            *(float4*)(C + gb) = o;
        } else if (EPI == 2){
            const float4 b4 = *(const float4*)(bias + bn + cq);
            float v0 = fmaxf(a0 + b4.x, 0.f), v1 = fmaxf(a1 + b4.y, 0.f);
            float v2 = fmaxf(a2 + b4.z, 0.f), v3 = fmaxf(a3 + b4.w, 0.f);
            *(__half2*)((__half*)Oh + gb)     = __floats2half2_rn(v0, v1);
            *(__half2*)((__half*)Oh + gb + 2) = __floats2half2_rn(v2, v3);
        } else if (EPI == 3){
            const float4 b4 = *(const float4*)(bias + bn + cq);
            const float4 r4 = *(const float4*)(res + gb);
            float4 o = {a0 + b4.x + r4.x, a1 + b4.y + r4.y,
                        a2 + b4.z + r4.z, a3 + b4.w + r4.w};
            *(float4*)(C + gb) = o;
        } else {
            const int col = bn + cq;
            const int sel = col >> 10;
            const int h   = (col & 1023) >> 6;
            const int d   = col & 63;
            const int tv  = bm + row;
            const size_t bhs = ((size_t)(((tv >> 11)*HH) + h)*SS + (tv & 2047));
            const float QSC = 0.125f * 1.44269504088896340736f;
            if (sel == 0){
                __nv_bfloat162 o0; o0.x = __float2bfloat16(a0*QSC); o0.y = __float2bfloat16(a1*QSC);
                __nv_bfloat162 o1; o1.x = __float2bfloat16(a2*QSC); o1.y = __float2bfloat16(a3*QSC);
                *(__nv_bfloat162*)(Oh + bhs*96 + d)     = o0;
                *(__nv_bfloat162*)(Oh + bhs*96 + d + 2) = o1;
            } else if (sel == 1){
                __nv_bfloat162 o0; o0.x = __float2bfloat16(a0); o0.y = __float2bfloat16(a1);
                __nv_bfloat162 o1; o1.x = __float2bfloat16(a2); o1.y = __float2bfloat16(a3);
                *(__nv_bfloat162*)(Ol + bhs*96 + d)     = o0;
                *(__nv_bfloat162*)(Ol + bhs*96 + d + 2) = o1;
            } else {
                __nv_bfloat162 o0; o0.x = __float2bfloat16(a0); o0.y = __float2bfloat16(a1);
                __nv_bfloat162 o1; o1.x = __float2bfloat16(a2); o1.y = __float2bfloat16(a3);
                *(__nv_bfloat162*)(Vo + bhs*64 + d)     = o0;
                *(__nv_bfloat162*)(Vo + bhs*64 + d + 2) = o1;
            }
        }
    }
}

// ============ weight prep, split for stream overlap ============
__device__ __forceinline__ void wtile(const float* W, __nv_bfloat16* T,
                                      int K, int N, int bx, int by, int f16,
                                      float* tptr)
{
    float (*t)[33] = (float(*)[33])tptr;
    const int tx = threadIdx.x & 31, ty = threadIdx.x >> 5;
    const int k0 = by*32, n0 = bx*32;
    #pragma unroll
    for (int i = 0; i < 4; i++)
        t[ty + i*8][tx] = W[(size_t)(k0 + ty + i*8)*N + n0 + tx];
    __syncthreads();
    #pragma unroll
    for (int i = 0; i < 4; i++){
        const int n = n0 + ty + i*8;
        const float x = t[tx][ty + i*8];
        if (f16) ((__half*)T)[(size_t)n*K + k0 + tx] = __float2half(x);
        else     T[(size_t)n*K + k0 + tx] = __float2bfloat16(x);
    }
}

__global__ __launch_bounds__(256) void wprep_qkv(
    const float* __restrict__ Wq, const float* __restrict__ Wk,
    const float* __restrict__ Wv,
    const float* __restrict__ Whq, const float* __restrict__ Whk)
{
    __shared__ float t[32][33];
    const int id = blockIdx.x;
    if (id < 3072){
        const int s = id >> 10, r = id & 1023;
        const float* W = s == 0 ? Wq : (s == 1 ? Wk : Wv);
        wtile(W, g_wqkvh + (size_t)s*DD*DD, DD, DD, r & 31, r >> 5, 0, &t[0][0]);
    } else {
        const int idx = id - 3072;                // 0..31
        const int m = idx >> 4, h = idx & 15;
        const float* src = m ? Whk : Whq;
        const float sc = m ? 1.f : (1.f/(0.125f*1.44269504088896340736f));
        for (int i = threadIdx.x; i < DHH*NBB; i += 256){
            const int f = i >> 5, n = i & 31;
            g_wt[(((size_t)m*HH + h)*NBB + n)*64 + f] =
                __float2bfloat16(src[((size_t)h*DHH + f)*NBB + n]*sc);
        }
    }
}

__global__ __launch_bounds__(256) void wprep_rest(
    const float* __restrict__ Wo, const float* __restrict__ W1,
    const float* __restrict__ W2)
{
    __shared__ float t[32][33];
    const int id = blockIdx.x;
    if (id < 1024)       wtile(Wo, g_woh, DD, DD, id & 31, id >> 5, 0, &t[0][0]);
    else if (id < 5120){ const int r = id - 1024; wtile(W1, g_w1, DD, MLPD, r & 127, r >> 7, 1, &t[0][0]); }
    else               { const int r = id - 5120; wtile(W2, g_w2, MLPD, DD, r & 31, r >> 5, 1, &t[0][0]); }
}

// ============ LayerNorm: MODE 0 = bf16 out, 1 = fp16 out ============
template<int MODE>
__global__ __launch_bounds__(256) void ln_split(
    const float* __restrict__ in, const float* __restrict__ g,
    const float* __restrict__ bta, __nv_bfloat16* __restrict__ oh)
{
    __shared__ float red[256];
    const int t = blockIdx.x, tid = threadIdx.x;
    const float4 x = ((const float4*)(in + (size_t)t*DD))[tid];

    float sum = x.x + x.y + x.z + x.w;
    red[tid] = sum; __syncthreads();
    #pragma unroll
    for (int o = 128; o > 0; o >>= 1) { if (tid < o) red[tid] += red[tid+o]; __syncthreads(); }
    const float mu = red[0] * (1.0f/DD);
    __syncthreads();

    float d0 = x.x-mu, d1 = x.y-mu, d2 = x.z-mu, d3 = x.w-mu;
    red[tid] = d0*d0 + d1*d1 + d2*d2 + d3*d3; __syncthreads();
    #pragma unroll
    for (int o = 128; o > 0; o >>= 1) { if (tid < o) red[tid] += red[tid+o]; __syncthreads(); }
    const float rs = rsqrtf(red[0]*(1.0f/DD) + 1e-6f);

    const float4 gg = ((const float4*)g)[tid];
    const float4 bb = ((const float4*)bta)[tid];
    float y0 = d0*rs*gg.x + bb.x, y1 = d1*rs*gg.y + bb.y;
    float y2 = d2*rs*gg.z + bb.z, y3 = d3*rs*gg.w + bb.w;

    if (MODE == 0){
        __nv_bfloat162 hp0; hp0.x = __float2bfloat16(y0); hp0.y = __float2bfloat16(y1);
        __nv_bfloat162 hp1; hp1.x = __float2bfloat16(y2); hp1.y = __float2bfloat16(y3);
        __nv_bfloat162* ph = (__nv_bfloat162*)(oh + (size_t)t*DD);
        ph[tid*2] = hp0; ph[tid*2 + 1] = hp1;
    } else {
        __half2* ph = (__half2*)((__half*)oh + (size_t)t*DD);
        ph[tid*2]     = __floats2half2_rn(y0, y1);
        ph[tid*2 + 1] = __floats2half2_rn(y2, y3);
    }
}

// ============ bucket softmax via mma (static shift) + fused partial sums ============
#define B2SM 41472
__global__ __launch_bounds__(128) void bucket2(
    const __nv_bfloat16* __restrict__ Qa, const __nv_bfloat16* __restrict__ Ka,
    const __nv_bfloat16* __restrict__ WT, float* __restrict__ bpart,
    __nv_bfloat16* __restrict__ Qao, __nv_bfloat16* __restrict__ Kao)
{
    extern __shared__ char sm[];
    const uint32_t smu = smem_u32(sm);
    const int tid = threadIdx.x, wid = tid >> 5, lane = tid & 31;
    const int h = blockIdx.x;
    const int ty = blockIdx.y, bq = ty >> 4, sbase = (ty & 15)*128;
    const int bh = bq*HH + h;
    const uint32_t Qs = smu, Ks = smu + 16384u, Ws = smu + 32768u;
    float* csum = (float*)(sm + 40960);

    const size_t qa0 = ((size_t)bh*SS + sbase)*96;
    for (int i = tid; i < 128*8; i += 128){
        const int r = i >> 3, c = i & 7;
        const uint32_t off = (uint32_t)(r*128) + (uint32_t)((c ^ (r & 7)) << 4);
        CPA16(Qs + off, (const char*)(Qa + qa0 + (size_t)r*96 + c*8));
        CPA16(Ks + off, (const char*)(Ka + qa0 + (size_t)r*96 + c*8));
    }
    for (int i = tid; i < 2*32*8; i += 128){
        const int m = i >> 8, r = (i >> 3) & 31, c = i & 7;
        CPA16(Ws + (uint32_t)(m*4096) + (uint32_t)(r*128) + (uint32_t)((c ^ (r & 7)) << 4),
              (const char*)(WT + ((size_t)m*HH + h)*NBB*64 + (size_t)r*64 + c*8));
    }
    CP_COMMIT(); CP_WAIT0(); __syncthreads();

    const int grp = lane >> 3, rin = lane & 7;
    const int roff = (grp & 1)*8 + rin, chi = grp >> 1;
    const float BSC = 0.1f * 1.44269504088896340736f;

    #pragma unroll
    for (int m = 0; m < 2; m++){
        const uint32_t As = m ? Ks : Qs;
        const uint32_t Bs = Ws + (uint32_t)m*4096u;
        float acc[2][4][4];
        #pragma unroll
        for (int mi = 0; mi < 2; mi++)
            #pragma unroll
            for (int nj = 0; nj < 4; nj++)
                #pragma unroll
                for (int e = 0; e < 4; e++) acc[mi][nj][e] = 0.f;

        #pragma unroll
        for (int ks = 0; ks < 4; ks++){
            uint32_t fa[2][4], fb0[4], fb1[4];
            #pragma unroll
            for (int mi = 0; mi < 2; mi++){
                const int r = wid*32 + mi*16 + roff;
                LDSM4(fa[mi], As + (uint32_t)(r*128) + (uint32_t)(((2*ks + chi) ^ (r & 7)) << 4));
            }
            { const int r = roff;      LDSM4(fb0, Bs + (uint32_t)(r*128) + (uint32_t)(((2*ks + chi) ^ (r & 7)) << 4)); }
            { const int r = 16 + roff; LDSM4(fb1, Bs + (uint32_t)(r*128) + (uint32_t)(((2*ks + chi) ^ (r & 7)) << 4)); }
            #pragma unroll
            for (int mi = 0; mi < 2; mi++){
                MMA16816(acc[mi][0], fa[mi], fb0[0], fb0[2]);
                MMA16816(acc[mi][1], fa[mi], fb0[1], fb0[3]);
                MMA16816(acc[mi][2], fa[mi], fb1[0], fb1[2]);
                MMA16816(acc[mi][3], fa[mi], fb1[1], fb1[3]);
            }
        }

        float local8[8];
        #pragma unroll
        for (int e = 0; e < 8; e++) local8[e] = 0.f;

        #pragma unroll
        for (int mi = 0; mi < 2; mi++){
            float s0v = 0.f, s1v = 0.f;
            #pragma unroll
            for (int nj = 0; nj < 4; nj++){
                acc[mi][nj][0] = __expf(acc[mi][nj][0]); s0v += acc[mi][nj][0];
                acc[mi][nj][1] = __expf(acc[mi][nj][1]); s0v += acc[mi][nj][1];
                acc[mi][nj][2] = __expf(acc[mi][nj][2]); s1v += acc[mi][nj][2];
                acc[mi][nj][3] = __expf(acc[mi][nj][3]); s1v += acc[mi][nj][3];
            }
            s0v += __shfl_xor_sync(~0u, s0v, 1); s0v += __shfl_xor_sync(~0u, s0v, 2);
            s1v += __shfl_xor_sync(~0u, s1v, 1); s1v += __shfl_xor_sync(~0u, s1v, 2);
            const float i0 = 1.f/s0v, i1 = 1.f/s1v;
            const int r_lo = wid*32 + mi*16 + (lane >> 2);
            const int srow0 = sbase + r_lo, srow1 = srow0 + 8;
            __nv_bfloat16* oo = m ? Kao : Qao;
            const float sc = m ? 1.f : BSC;
            #pragma unroll
            for (int nj = 0; nj < 4; nj++){
                const int cc = nj*8 + (lane & 3)*2;
                float p0 = acc[mi][nj][0]*i0, p1 = acc[mi][nj][1]*i0;
                float p2 = acc[mi][nj][2]*i1, p3 = acc[mi][nj][3]*i1;
                local8[nj*2]     += p0 + p2;
                local8[nj*2 + 1] += p1 + p3;
                __nv_bfloat162 o0; o0.x = __float2bfloat16(p0*sc); o0.y = __float2bfloat16(p1*sc);
                __nv_bfloat162 o1; o1.x = __float2bfloat16(p2*sc); o1.y = __float2bfloat16(p3*sc);
                *(__nv_bfloat162*)(oo + ((size_t)bh*SS + srow0)*96 + 64 + cc) = o0;
                *(__nv_bfloat162*)(oo + ((size_t)bh*SS + srow1)*96 + 64 + cc) = o1;
            }
        }

        #pragma unroll
        for (int e = 0; e < 8; e++){
            local8[e] += __shfl_down_sync(~0u, local8[e], 16);
            local8[e] += __shfl_down_sync(~0u, local8[e], 8);
            local8[e] += __shfl_down_sync(~0u, local8[e], 4);
        }
        if ((lane >> 2) == 0){
            #pragma unroll
            for (int nj = 0; nj < 4; nj++){
                csum[wid*32 + nj*8 + lane*2]     = local8[nj*2];
                csum[wid*32 + nj*8 + lane*2 + 1] = local8[nj*2 + 1];
            }
        }
        __syncthreads();
        if (tid < 32){
            const float v = csum[tid] + csum[32 + tid] + csum[64 + tid] + csum[96 + tid];
            bpart[(((size_t)m*HH + h)*NT + ty)*NBB + tid] = v;
        }
        __syncthreads();
    }
}

// ============ flash attention: static-shift softmax ============
#define FSM 65536
#define CSH 24.0f
__global__ __launch_bounds__(256, 2) void flash_mma(
    const __nv_bfloat16* __restrict__ Qa, const __nv_bfloat16* __restrict__ Ka,
    const __nv_bfloat16* __restrict__ Vb, __nv_bfloat16* __restrict__ ah)
{
    extern __shared__ char sm[];
    const uint32_t smu = smem_u32(sm);
    const int tid = threadIdx.x, wid = tid >> 5, lane = tid & 31;
    const int bh = blockIdx.x, b = bh >> 4, h = bh & 15;
    const int q0 = blockIdx.y * 128;

    const uint32_t QC = smu, QB = smu + 16384u;
    const uint32_t ST0 = smu + 24576u;

    {
        const size_t qb0 = ((size_t)bh*SS + q0)*96;
        #pragma unroll
        for (int i = 0; i < 4; i++){
            const int q = tid + i*256, r = q >> 3, c = q & 7;
            CPA16(QC + (uint32_t)(r*128) + (uint32_t)(((c ^ (r & 7)) << 4)),
                  (const char*)(Qa + qb0 + (size_t)r*96 + c*8));
        }
        #pragma unroll
        for (int i = 0; i < 2; i++){
            const int q = tid + i*256, r = q >> 2, c = q & 3;
            CPA16(QB + (uint32_t)(r*64) + (uint32_t)(((c ^ ((r >> 1) & 3)) << 4)),
                  (const char*)(Qa + qb0 + (size_t)r*96 + 64 + c*8));
        }
        CP_COMMIT();
    }
    auto issueKV = [&](int it, uint32_t st){
        const size_t kb0 = ((size_t)bh*SS + it*64)*96;
        const size_t vb0 = ((size_t)bh*SS + it*64)*64;
        #pragma unroll
        for (int i = 0; i < 2; i++){
            const int q = tid + i*256, r = q >> 3, c = q & 7;
            CPA16(st + (uint32_t)(r*128) + (uint32_t)((c ^ (r & 7)) << 4),
                  (const char*)(Ka + kb0 + (size_t)r*96 + c*8));
        }
        {
            const int r = tid >> 2, c = tid & 3;
            CPA16(st + 8192u + (uint32_t)(r*64) + (uint32_t)((c ^ ((r >> 1) & 3)) << 4),
                  (const char*)(Ka + kb0 + (size_t)r*96 + 64 + c*8));
        }
        #pragma unroll
        for (int i = 0; i < 2; i++){
            const int q = tid + i*256, r = q >> 3, c = q & 7;
            CPA16(st + 12288u + (uint32_t)(r*128) + (uint32_t)((c ^ (r & 7)) << 4),
                  (const char*)(Vb + vb0 + (size_t)r*64 + c*8));
        }
        CP_COMMIT();
    };
    issueKV(0, ST0);
    issueKV(1, ST0 + 20480u);

    CP_WAIT2();
    __syncthreads();

    const int grp = lane >> 3, rin = lane & 7;
    const int roff = (grp & 1)*8 + rin, chi = grp >> 1;

    uint32_t qf[6][4];
    {
        const int r = wid*16 + roff;
        #pragma unroll
        for (int ks = 0; ks < 4; ks++)
            LDSM4(qf[ks], QC + (uint32_t)(r*128) + (uint32_t)(((2*ks + chi) ^ (r & 7)) << 4));
        #pragma unroll
        for (int ks = 0; ks < 2; ks++)
            LDSM4(qf[4 + ks], QB + (uint32_t)(r*64) + (uint32_t)(((2*ks + chi) ^ ((r >> 1) & 3)) << 4));
    }

    float oacc[8][4];
    #pragma unroll
    for (int nt = 0; nt < 8; nt++)
        #pragma unroll
        for (int e = 0; e < 4; e++) oacc[nt][e] = 0.f;
    float l0 = 0.f, l1 = 0.f;

    for (int it = 0; it < SS/64; it++){
        const uint32_t st = ST0 + (uint32_t)(it & 1)*20480u;
        if (it + 1 < SS/64) CP_WAIT1(); else CP_WAIT0();
        __syncthreads();

        float sacc[8][4];
        #pragma unroll
        for (int nt = 0; nt < 8; nt++)
            #pragma unroll
            for (int e = 0; e < 4; e++) sacc[nt][e] = 0.f;

        #pragma unroll
        for (int ks = 0; ks < 6; ks++){
            #pragma unroll
            for (int p = 0; p < 4; p++){
                uint32_t bf[4];
                const int r = p*16 + roff;
                if (ks < 4)
                    LDSM4(bf, st + (uint32_t)(r*128) + (uint32_t)(((2*ks + chi) ^ (r & 7)) << 4));
                else
                    LDSM4(bf, st + 8192u + (uint32_t)(r*64) + (uint32_t)(((2*(ks-4) + chi) ^ ((r >> 1) & 3)) << 4));
                MMA16816(sacc[2*p],     qf[ks], bf[0], bf[2]);
                MMA16816(sacc[2*p + 1], qf[ks], bf[1], bf[3]);
            }
        }

        #pragma unroll
        for (int nt = 0; nt < 8; nt++){
            sacc[nt][0] = exp2f(sacc[nt][0] - CSH); l0 += sacc[nt][0];
            sacc[nt][1] = exp2f(sacc[nt][1] - CSH); l0 += sacc[nt][1];
            sacc[nt][2] = exp2f(sacc[nt][2] - CSH); l1 += sacc[nt][2];
            sacc[nt][3] = exp2f(sacc[nt][3] - CSH); l1 += sacc[nt][3];
        }

        uint32_t pf[4][4];
        #pragma unroll
        for (int kk = 0; kk < 4; kk++){
            PACKBF(pf[kk][0], sacc[2*kk][0],     sacc[2*kk][1]);
            PACKBF(pf[kk][1], sacc[2*kk][2],     sacc[2*kk][3]);
            PACKBF(pf[kk][2], sacc[2*kk + 1][0], sacc[2*kk + 1][1]);
            PACKBF(pf[kk][3], sacc[2*kk + 1][2], sacc[2*kk + 1][3]);
        }

        #pragma unroll
        for (int kk = 0; kk < 4; kk++){
            #pragma unroll
            for (int p = 0; p < 4; p++){
                uint32_t bv[4];
                const int vrow = kk*16 + (grp >> 1)*8 + rin;
                LDSM4T(bv, st + 12288u + (uint32_t)(vrow*128)
                           + (uint32_t)(((2*p + (grp & 1)) ^ (vrow & 7)) << 4));
                MMA16816(oacc[2*p],     pf[kk], bv[0], bv[2]);
                MMA16816(oacc[2*p + 1], pf[kk], bv[1], bv[3]);
            }
        }
        __syncthreads();
        if (it + 2 < SS/64) issueKV(it + 2, st);
    }

    l0 += __shfl_xor_sync(0xffffffffu, l0, 1);
    l0 += __shfl_xor_sync(0xffffffffu, l0, 2);
    l1 += __shfl_xor_sync(0xffffffffu, l1, 1);
    l1 += __shfl_xor_sync(0xffffffffu, l1, 2);
    const float inv0 = 1.f / l0, inv1 = 1.f / l1;
    const int r0g = q0 + wid*16 + (lane >> 2);
    const size_t t0 = (size_t)(b*SS + r0g), t1 = t0 + 8;
    const int cb = h*DHH + 2*(lane & 3);
    #pragma unroll
    for (int j = 0; j < 8; j++){
        const float v0 = oacc[j][0]*inv0, v1 = oacc[j][1]*inv0;
        const float v2 = oacc[j][2]*inv1, v3 = oacc[j][3]*inv1;
        __nv_bfloat162 hp0; hp0.x = __float2bfloat16(v0); hp0.y = __float2bfloat16(v1);
        __nv_bfloat162 hp1; hp1.x = __float2bfloat16(v2); hp1.y = __float2bfloat16(v3);
        *(__nv_bfloat162*)(ah + t0*DD + cb + 8*j) = hp0;
        *(__nv_bfloat162*)(ah + t1*DD + cb + 8*j) = hp1;
    }
}

// ============ aux loss ============
__global__ __launch_bounds__(512) void msum_loss(
    const float* __restrict__ bpart, float* __restrict__ out, int out_idx)
{
    __shared__ float red[512];
    const int tid = threadIdx.x;
    const int h = tid >> 5, n = tid & 31;
    float sq = 0.f, sk = 0.f;
    #pragma unroll 8
    for (int t = 0; t < NT; t++){
        sq += bpart[(((size_t)0*HH + h)*NT + t)*NBB + n];
        sk += bpart[(((size_t)1*HH + h)*NT + t)*NBB + n];
    }
    const float mq = sq * (1.0f/TOK), mk = sk * (1.0f/TOK);
    red[tid] = mq*mq + mk*mk; __syncthreads();
    #pragma unroll
    for (int o = 256; o > 0; o >>= 1) { if (tid < o) red[tid] += red[tid+o]; __syncthreads(); }
    if (tid == 0) out[out_idx] = 0.5f * (float)NBB * red[0] / (float)HH;
}

// ============ host launch: fork/join side stream for weight prep + aux loss ============
extern "C" void kernel_launch(void* const* d_in, const int* in_sizes, int n_in,
                              void* d_out, int out_size)
{
    const float* inputs = (const float*)d_in[0];
    const float* ln1_g  = (const float*)d_in[1];
    const float* ln1_b  = (const float*)d_in[2];
    const float* Wq     = (const float*)d_in[3];
    const float* Wk     = (const float*)d_in[4];
    const float* Wv     = (const float*)d_in[5];
    const float* Whq    = (const float*)d_in[6];
    const float* Whk    = (const float*)d_in[7];
    const float* Wo     = (const float*)d_in[8];
    const float* ln2_g  = (const float*)d_in[9];
    const float* ln2_b  = (const float*)d_in[10];
    const float* W1     = (const float*)d_in[11];
    const float* b1     = (const float*)d_in[12];
    const float* W2     = (const float*)d_in[13];
    const float* b2     = (const float*)d_in[14];
    float* out = (float*)d_out;

    __nv_bfloat16 *p_xh, *p_ah, *p_y, *p_h1;
    __nv_bfloat16 *p_wqkvh, *p_woh, *p_w1, *p_w2;
    __nv_bfloat16 *p_Qa, *p_Ka, *p_Vb, *p_wt;
    float *p_x, *p_bpart;
    cudaGetSymbolAddress((void**)&p_xh, g_xh);
    cudaGetSymbolAddress((void**)&p_ah, g_ah);
    cudaGetSymbolAddress((void**)&p_x, g_x);
    cudaGetSymbolAddress((void**)&p_y, g_y);
    cudaGetSymbolAddress((void**)&p_h1, g_h1);
    cudaGetSymbolAddress((void**)&p_bpart, g_bpart);
    cudaGetSymbolAddress((void**)&p_wqkvh, g_wqkvh);
    cudaGetSymbolAddress((void**)&p_woh, g_woh);
    cudaGetSymbolAddress((void**)&p_w1, g_w1);
    cudaGetSymbolAddress((void**)&p_w2, g_w2);
    cudaGetSymbolAddress((void**)&p_Qa, g_Qa);   cudaGetSymbolAddress((void**)&p_Ka, g_Ka);
    cudaGetSymbolAddress((void**)&p_Vb, g_Vb);   cudaGetSymbolAddress((void**)&p_wt, g_wt);

    cudaFuncSetAttribute((const void*)mma_gemm<4,0>, cudaFuncAttributeMaxDynamicSharedMemorySize, GSM);
    cudaFuncSetAttribute((const void*)mma_gemm<1,0>, cudaFuncAttributeMaxDynamicSharedMemorySize, GSM);
    cudaFuncSetAttribute((const void*)mma_gemm<2,1>, cudaFuncAttributeMaxDynamicSharedMemorySize, GSM);
    cudaFuncSetAttribute((const void*)mma_gemm<3,1>, cudaFuncAttributeMaxDynamicSharedMemorySize, GSM);
    cudaFuncSetAttribute((const void*)flash_mma, cudaFuncAttributeMaxDynamicSharedMemorySize, FSM);
    cudaFuncSetAttribute((const void*)bucket2, cudaFuncAttributeMaxDynamicSharedMemorySize, B2SM);

    cudaStream_t s2;
    cudaStreamCreateWithFlags(&s2, cudaStreamNonBlocking);
    cudaEvent_t evF, evJ, evB, evM;
    cudaEventCreateWithFlags(&evF, cudaEventDisableTiming);
    cudaEventCreateWithFlags(&evJ, cudaEventDisableTiming);
    cudaEventCreateWithFlags(&evB, cudaEventDisableTiming);
    cudaEventCreateWithFlags(&evM, cudaEventDisableTiming);

    // fork: side stream preps Wo/W1/W2 while main stream runs ln1 -> qkv prep -> QKV
    cudaEventRecord(evF, 0);
    cudaStreamWaitEvent(s2, evF, 0);
    wprep_rest<<<9216, 256, 0, s2>>>(Wo, W1, W2);                                  // k1 (s2)
    cudaEventRecord(evJ, s2);

    ln_split<0><<<TOK, 256>>>(inputs, ln1_g, ln1_b, p_xh);                         // k2
    wprep_qkv<<<3104, 256>>>(Wq, Wk, Wv, Whq, Whk);                                // k3
    mma_gemm<4,0><<<dim3(QKVD/128, TOK/128), 256, GSM>>>(                          // k4: QKV
        p_xh, p_wqkvh, nullptr, nullptr, nullptr, p_Qa, p_Ka, p_Vb,
        TOK, QKVD, DD);
    bucket2<<<dim3(HH, NT), 128, B2SM>>>(p_Qa, p_Ka, p_wt, p_bpart, p_Qa, p_Ka);   // k5
    flash_mma<<<dim3(BH, SS/128), 256, FSM>>>(p_Qa, p_Ka, p_Vb, p_ah);             // k6 (profiled)

    // fork: aux loss overlaps Wo GEMM
    cudaEventRecord(evB, 0);
    cudaStreamWaitEvent(s2, evB, 0);
    msum_loss<<<1, 512, 0, s2>>>(p_bpart, out, out_size - 1);                      // k7 (s2)
    cudaEventRecord(evM, s2);

    cudaStreamWaitEvent(0, evJ, 0);   // join weight prep before Wo GEMM
    mma_gemm<1,0><<<dim3(DD/128, TOK/128), 256, GSM>>>(                            // k8: Wo + residual
        p_ah, p_woh, p_x, nullptr, inputs, nullptr, nullptr, nullptr,
        TOK, DD, DD);
    ln_split<1><<<TOK, 256>>>(p_x, ln2_g, ln2_b, p_y);                             // k9
    mma_gemm<2,1><<<dim3(MLPD/128, TOK/128), 256, GSM>>>(                          // k10: MLP1 fp16
        p_y, p_w1, nullptr, b1, nullptr, p_h1, nullptr, nullptr,
        TOK, MLPD, DD);
    mma_gemm<3,1><<<dim3(DD/128, TOK/128), 256, GSM>>>(                            // k11: MLP2 fp16
        p_h1, p_w2, out, b2, p_x, nullptr, nullptr, nullptr,
        TOK, DD, MLPD);
    cudaStreamWaitEvent(0, evM, 0);   // join aux loss before return
}